// round 13
// baseline (speedup 1.0000x reference)
#include <cuda_runtime.h>
#include <cuda_fp16.h>
#include <math.h>
#include <stdint.h>

#define B_    8
#define C_    512
#define H_    64
#define W_    64
#define N_    4096          // H*W
#define AREA_ 4
#define NHEAD 8
#define HD_   64
#define NA_   1024          // N/AREA
#define EPS_  1e-5f

// ---------------- scratch (device globals; no allocation allowed) ----------
__device__ __half g_xt  [B_ * N_ * C_];        // x^T  [b][n][c]
__device__ __half g_wqkh[2 * C_ * C_];         // weights, half row-major
__device__ __half g_wvh [C_ * C_];
__device__ __half g_wprh[C_ * C_];
__device__ __half g_wpeh[9 * 32 * 512 * 16];   // conv w [tap][ci][o][16]
__device__ __half g_qkT [B_ * N_ * 2 * C_];    // qk act, token-major [b][n][2C]
__device__ __half g_vh  [B_ * C_ * N_];        // v act [b][c][n]
__device__ __half g_vT  [B_ * N_ * C_];        // v act transposed [b][n][c]
__device__ __half g_ppT [B_ * N_ * C_];        // conv3 out, token-major
__device__ __half g_attT[B_ * N_ * C_];        // attention out, token-major

__device__ __forceinline__ float silu_f(float y) {
    return y / (1.0f + __expf(-y));
}
__device__ __forceinline__ unsigned h2f(float a, float b) {
    __half2 h = __floats2half2_rn(a, b);
    return *reinterpret_cast<unsigned*>(&h);
}
// D += A*B, m16n8k16 f16 in / f32 accum, row.col
__device__ __forceinline__ void mma16(float* c, const unsigned* a, const unsigned* b) {
    asm volatile(
      "mma.sync.aligned.m16n8k16.row.col.f32.f16.f16.f32 "
      "{%0,%1,%2,%3},{%4,%5,%6,%7},{%8,%9},{%0,%1,%2,%3};"
      : "+f"(c[0]), "+f"(c[1]), "+f"(c[2]), "+f"(c[3])
      : "r"(a[0]), "r"(a[1]), "r"(a[2]), "r"(a[3]), "r"(b[0]), "r"(b[1]));
}
// 4x 8x8 b16 matrices in one instruction
__device__ __forceinline__ void ldsm4(unsigned* r, uint32_t addr) {
    asm volatile("ldmatrix.sync.aligned.m8n8.x4.shared.b16 {%0,%1,%2,%3}, [%4];"
        : "=r"(r[0]), "=r"(r[1]), "=r"(r[2]), "=r"(r[3]) : "r"(addr));
}
__device__ __forceinline__ void cpa16(void* dst, const void* src) {
    unsigned d = (unsigned)__cvta_generic_to_shared(dst);
    asm volatile("cp.async.cg.shared.global [%0], [%1], 16;" :: "r"(d), "l"(src));
}
__device__ __forceinline__ void cpa16z(void* dst, const void* src, unsigned sz) {
    unsigned d = (unsigned)__cvta_generic_to_shared(dst);
    asm volatile("cp.async.cg.shared.global [%0], [%1], 16, %2;" :: "r"(d), "l"(src), "r"(sz));
}
__device__ __forceinline__ void cpa_commit() { asm volatile("cp.async.commit_group;"); }
__device__ __forceinline__ void cpa_wait1()  { asm volatile("cp.async.wait_group 1;"); }
__device__ __forceinline__ void cpa_wait0()  { asm volatile("cp.async.wait_group 0;"); }

// ============================================================================
// Prep kernels
// ============================================================================
__global__ void f2h_k(const float4* __restrict__ in, uint4* __restrict__ out, int n8)
{
    int i = blockIdx.x * blockDim.x + threadIdx.x;
    if (i < n8) {
        float4 a = in[2 * i], b = in[2 * i + 1];
        out[i] = make_uint4(h2f(a.x, a.y), h2f(a.z, a.w), h2f(b.x, b.y), h2f(b.z, b.w));
    }
}

// x [b][c][n] fp32 -> g_xt [b][n][c] half
__global__ void xpose_h(const float* __restrict__ x, __half* __restrict__ xt)
{
    __shared__ float ts[32][33];
    const int b  = blockIdx.z;
    const int c0 = blockIdx.y * 32;
    const int nb = blockIdx.x * 32;
    const int tx = threadIdx.x, ty = threadIdx.y;   // 32 x 8
    const float* xb = x + ((size_t)b * C_ + c0) * N_ + nb;
    #pragma unroll
    for (int i = 0; i < 4; i++) {
        int c = ty + i * 8;
        ts[c][tx] = xb[(size_t)c * N_ + tx];
    }
    __syncthreads();
    const int e0 = ty * 32 + tx;
    #pragma unroll
    for (int i = 0; i < 2; i++) {
        int idx = i * 256 + e0;
        int n = idx >> 4, w = idx & 15;
        unsigned word = h2f(ts[2 * w][n], ts[2 * w + 1][n]);
        ((unsigned*)(xt + ((size_t)b * N_ + nb + n) * C_ + c0))[w] = word;
    }
}

// pe_w [O][I][3][3] fp32 -> g_wpeh [tap][ci][o][16] half
__global__ void conv_w_xform_h(const float* __restrict__ pe_w, __half* __restrict__ wp)
{
    int idx = blockIdx.x * 256 + threadIdx.x;
    if (idx >= 9 * 32 * 512 * 16) return;
    int cl  = idx & 15;
    int o   = (idx >> 4) & 511;
    int ci  = (idx >> 13) & 31;
    int tap = idx >> 18;
    wp[idx] = __float2half_rn(pe_w[((size_t)o * C_ + ci * 16 + cl) * 9 + tap]);
}

// ============================================================================
// fp16 GEMM + BN + SiLU, ldmatrix fragments.  (unchanged)
// ============================================================================
#define GH_STG 5120   // words/stage: A 128*20 + B 128*20

__global__ __launch_bounds__(256, 2)
void gemm_h(const __half* __restrict__ Wt,
            const __half* __restrict__ Xt,
            const float* __restrict__ gg, const float* __restrict__ bb,
            const float* __restrict__ rm, const float* __restrict__ rv,
            __half* __restrict__ Yt,      // [b][n][M]
            __half* __restrict__ Yc,      // [b][m][N] or null
            int M)
{
    extern __shared__ unsigned sm[];     // 2 * GH_STG words

    const int n0 = blockIdx.x * 128;
    const int m0 = blockIdx.y * 128;
    const int b  = blockIdx.z;
    const __half* Wb = Wt + (size_t)m0 * C_;
    const __half* Xb = Xt + ((size_t)b * N_ + n0) * C_;

    const int tid = threadIdx.x, lane = tid & 31, warp = tid >> 5;
    const int g = lane >> 2, t = lane & 3;
    const int wm = warp >> 1, wn = warp & 1;
    const int mrow = lane & 7, msel = lane >> 3;
    const int mlo = msel & 1, mhi = msel >> 1;
    const uint32_t smb = (unsigned)__cvta_generic_to_shared(sm);

    float acc[2][8][4] = {};

    #define GH_ISSUE(CH, S) do {                                            \
        unsigned* bs = sm + (S) * GH_STG;                                   \
        _Pragma("unroll")                                                   \
        for (int i_ = 0; i_ < 4; i_++) {                                    \
            int e = tid + 256 * i_;                                         \
            int op = e >> 9, r = (e >> 2) & 127, q = e & 3;                 \
            const __half* src = (op ? Xb : Wb) + (size_t)r * C_ + (CH) * 32 + q * 8; \
            cpa16(bs + (op ? 2560 : 0) + r * 20 + q * 4, src);              \
        }                                                                   \
        cpa_commit();                                                       \
    } while (0)

    GH_ISSUE(0, 0);
    GH_ISSUE(1, 1);

    for (int ch = 0; ch < 16; ch++) {
        cpa_wait1();
        __syncthreads();
        const uint32_t sb = smb + (unsigned)((ch & 1) * (GH_STG * 4));
        const uint32_t xbse = sb + 2560 * 4;
        #pragma unroll
        for (int ks = 0; ks < 2; ks++) {
            unsigned a[2][4];
            #pragma unroll
            for (int mt = 0; mt < 2; mt++) {
                int row = wm * 32 + mt * 16 + mlo * 8 + mrow;
                ldsm4(a[mt], sb + (unsigned)((row * 20 + ks * 8 + mhi * 4) * 4));
            }
            #pragma unroll
            for (int ntp = 0; ntp < 4; ntp++) {
                unsigned bv[4];
                int row = wn * 64 + ntp * 16 + mhi * 8 + mrow;
                ldsm4(bv, xbse + (unsigned)((row * 20 + ks * 8 + mlo * 4) * 4));
                mma16(acc[0][2 * ntp],     a[0], bv);
                mma16(acc[0][2 * ntp + 1], a[0], bv + 2);
                mma16(acc[1][2 * ntp],     a[1], bv);
                mma16(acc[1][2 * ntp + 1], a[1], bv + 2);
            }
        }
        __syncthreads();
        if (ch + 2 < 16) GH_ISSUE(ch + 2, ch & 1);
        else             cpa_commit();
    }

    __half* hs = (__half*)sm;            // [128 n][136 m]
    #pragma unroll
    for (int mt = 0; mt < 2; mt++) {
        int R0 = wm * 32 + mt * 16 + g;
        int m  = m0 + R0, m1 = m + 8;
        float sc0 = gg[m]  * rsqrtf(rv[m]  + EPS_), sh0 = bb[m]  - rm[m]  * sc0;
        float sc1 = gg[m1] * rsqrtf(rv[m1] + EPS_), sh1 = bb[m1] - rm[m1] * sc1;
        #pragma unroll
        for (int nt = 0; nt < 8; nt++) {
            float* c = acc[mt][nt];
            float v0 = silu_f(c[0] * sc0 + sh0), v1 = silu_f(c[1] * sc0 + sh0);
            float v2 = silu_f(c[2] * sc1 + sh1), v3 = silu_f(c[3] * sc1 + sh1);
            int px0 = wn * 64 + nt * 8 + 2 * t;
            if (Yc) {
                *(unsigned*)(Yc + ((size_t)b * M + m)  * N_ + n0 + px0) = h2f(v0, v1);
                *(unsigned*)(Yc + ((size_t)b * M + m1) * N_ + n0 + px0) = h2f(v2, v3);
            }
            hs[px0 * 136 + R0]           = __float2half_rn(v0);
            hs[(px0 + 1) * 136 + R0]     = __float2half_rn(v1);
            hs[px0 * 136 + R0 + 8]       = __float2half_rn(v2);
            hs[(px0 + 1) * 136 + R0 + 8] = __float2half_rn(v3);
        }
    }
    __syncthreads();
    const unsigned* hw = (const unsigned*)hs;
    #pragma unroll
    for (int i = 0; i < 32; i++) {
        int e = tid + 256 * i;
        int n = e >> 6, w = e & 63;
        ((unsigned*)(Yt + ((size_t)b * N_ + n0 + n) * M + m0))[w] = hw[n * 68 + w];
    }
    #undef GH_ISSUE
}

// ============================================================================
// fp16 3x3 SAME conv + BN + SiLU.  64o x 512px (8 rows) tile, 512 threads,
// 16 warps (2o x 8px), ldmatrix + 2-stage cp.async ring.  grid (8, 8, B).
// ============================================================================
#define CV_AW  (9 * 64 * 12)            // 6912 words
#define CV_BX  (10 * 66 * 12)           // 7920 words
#define CV_STG (CV_AW + CV_BX)          // 14832 words per stage
#define CV_SMEM (2 * CV_STG * 4)        // 118656 B

__global__ __launch_bounds__(512, 1)
void conv3_h(const __half* __restrict__ Wp,
             const __half* __restrict__ vT,
             const float* __restrict__ gg, const float* __restrict__ bb,
             const float* __restrict__ rm, const float* __restrict__ rv,
             __half* __restrict__ ppT)
{
    extern __shared__ unsigned cs[];    // 2 stages: [Aw | Bx]

    const int y0 = blockIdx.x * 8;
    const int m0 = blockIdx.y * 64;
    const int b  = blockIdx.z;
    const __half* vTb = vT + (size_t)b * N_ * C_;

    const int tid = threadIdx.x, lane = tid & 31, warp = tid >> 5;
    const int g = lane >> 2, t = lane & 3;
    const int wm = warp >> 3, wn = warp & 7;   // 2o x 8px
    const int mrow = lane & 7, msel = lane >> 3;
    const int mlo = msel & 1, mhi = msel >> 1;
    const uint32_t csb = (unsigned)__cvta_generic_to_shared(cs);

    float acc[2][8][4] = {};

    #define CV_ISSUE(CI, S) do {                                               \
        unsigned* Aw_ = cs + (S) * CV_STG;                                     \
        unsigned* Bx_ = Aw_ + CV_AW;                                           \
        for (int e = tid; e < 1152; e += 512) {                                \
            int tap_ = e >> 7, r_ = (e >> 1) & 63, q_ = e & 1;                 \
            cpa16(Aw_ + (tap_ * 64 + r_) * 12 + q_ * 4,                        \
                  Wp + (((size_t)tap_ * 32 + (CI)) * 512 + m0 + r_) * 16 + q_ * 8); \
        }                                                                      \
        for (int e = tid; e < 1320; e += 512) {                                \
            int r_ = e / 132, rem_ = e - r_ * 132;                             \
            int p_ = rem_ >> 1, q_ = rem_ & 1;                                 \
            int gy_ = y0 - 1 + r_, gx_ = p_ - 1;                               \
            bool ok_ = (gy_ >= 0 && gy_ < H_ && gx_ >= 0 && gx_ < W_);         \
            const __half* src_ = vTb + (ok_ ? ((size_t)(gy_ * W_ + gx_) * C_ + (CI) * 16 + q_ * 8) : 0); \
            cpa16z(Bx_ + (r_ * 66 + p_) * 12 + q_ * 4, src_, ok_ ? 16u : 0u);  \
        }                                                                      \
        cpa_commit();                                                          \
    } while (0)

    CV_ISSUE(0, 0);
    CV_ISSUE(1, 1);

    for (int ci = 0; ci < 32; ci++) {
        cpa_wait1();
        __syncthreads();
        const uint32_t awb = csb + (unsigned)((ci & 1) * (CV_STG * 4));
        const uint32_t bxb = awb + CV_AW * 4;

        for (int tap = 0; tap < 9; tap++) {
            const int dy = tap / 3, dx = tap - dy * 3;
            unsigned a[2][4];
            #pragma unroll
            for (int mt = 0; mt < 2; mt++) {
                int row = tap * 64 + wm * 32 + mt * 16 + mlo * 8 + mrow;
                ldsm4(a[mt], awb + (unsigned)((row * 12 + mhi * 4) * 4));
            }
            const int rr = wn + dy;
            #pragma unroll
            for (int ntp = 0; ntp < 4; ntp++) {
                unsigned bv[4];
                int row = rr * 66 + ntp * 16 + mhi * 8 + mrow + dx;
                ldsm4(bv, bxb + (unsigned)((row * 12 + mlo * 4) * 4));
                mma16(acc[0][2 * ntp],     a[0], bv);
                mma16(acc[0][2 * ntp + 1], a[0], bv + 2);
                mma16(acc[1][2 * ntp],     a[1], bv);
                mma16(acc[1][2 * ntp + 1], a[1], bv + 2);
            }
        }
        __syncthreads();
        if (ci + 2 < 32) CV_ISSUE(ci + 2, ci & 1);
        else             cpa_commit();
    }
    #undef CV_ISSUE

    __syncthreads();
    __half* hs = (__half*)cs;        // [512 px][72 o]
    #pragma unroll
    for (int mt = 0; mt < 2; mt++) {
        int R0 = wm * 32 + mt * 16 + g;
        int m  = m0 + R0, m1 = m + 8;
        float sc0 = gg[m]  * rsqrtf(rv[m]  + EPS_), sh0 = bb[m]  - rm[m]  * sc0;
        float sc1 = gg[m1] * rsqrtf(rv[m1] + EPS_), sh1 = bb[m1] - rm[m1] * sc1;
        #pragma unroll
        for (int nt = 0; nt < 8; nt++) {
            float* c = acc[mt][nt];
            int P0 = wn * 64 + nt * 8 + 2 * t;
            hs[P0 * 72 + R0]           = __float2half_rn(silu_f(c[0] * sc0 + sh0));
            hs[(P0 + 1) * 72 + R0]     = __float2half_rn(silu_f(c[1] * sc0 + sh0));
            hs[P0 * 72 + R0 + 8]       = __float2half_rn(silu_f(c[2] * sc1 + sh1));
            hs[(P0 + 1) * 72 + R0 + 8] = __float2half_rn(silu_f(c[3] * sc1 + sh1));
        }
    }
    __syncthreads();
    const unsigned* hw = (const unsigned*)hs;
    #pragma unroll
    for (int i = 0; i < 32; i++) {
        int e = tid + 512 * i;
        int P = e >> 5, w = e & 31;
        ((unsigned*)(ppT + ((size_t)b * N_ + y0 * W_ + P) * C_ + m0))[w] = hw[P * 36 + w];
    }
}

// ============================================================================
// fp16 area attention (FA2), ldmatrix + 2-stage KV ring, zero shuffles.
// (unchanged from round 12)
// ============================================================================
#define AT_QS (128 * 36)
#define AT_KS (64 * 36)
#define AT_VS (64 * 36)
#define AT_KV (AT_KS + AT_VS)                 // 4608 words per stage
#define AT_SMEM ((AT_QS + 2 * AT_KV) * 4)     // 55296 B

__global__ __launch_bounds__(256, 2)
void attn_h(const __half* __restrict__ qkT,
            const __half* __restrict__ vh,
            __half* __restrict__ attT)
{
    extern __shared__ unsigned as_[];
    unsigned* Qs = as_;                   // [q][36]

    const int q0   = blockIdx.x * 128;
    const int head = blockIdx.y;
    const int ba   = blockIdx.z;
    const int b    = ba >> 2;
    const int area = ba & 3;
    const int atok = area * NA_;

    const __half* Qb = qkT + ((size_t)b * N_ + atok + q0) * (2 * C_) + head * HD_;
    const __half* Kb = qkT + ((size_t)b * N_ + atok) * (2 * C_) + C_ + head * HD_;
    const __half* Vb = vh  + ((size_t)b * C_ + head * HD_) * N_ + atok;
    __half*       Ob = attT + ((size_t)b * N_ + atok + q0) * C_ + head * HD_;

    const int tid = threadIdx.x, lane = tid & 31, warp = tid >> 5;
    const int g = lane >> 2, t = lane & 3;
    const int wq = warp * 16;
    const int mrow = lane & 7, msel = lane >> 3;
    const int mlo = msel & 1, mhi = msel >> 1;
    const uint32_t asb = (unsigned)__cvta_generic_to_shared(as_);

    // stage Q once: 128 rows x 32 words (its own commit group)
    #pragma unroll
    for (int i = 0; i < 4; i++) {
        int e = tid + 256 * i;
        int r = e >> 3, q = e & 7;
        cpa16(Qs + r * 36 + q * 4, Qb + (size_t)r * (2 * C_) + q * 8);
    }
    cpa_commit();

    #define AT_ISSUE(JT, S) do {                                              \
        unsigned* Ks_ = as_ + AT_QS + (S) * AT_KV;                            \
        unsigned* Vs_ = Ks_ + AT_KS;                                          \
        _Pragma("unroll")                                                     \
        for (int i_ = 0; i_ < 2; i_++) {                                      \
            int e = tid + 256 * i_;                                           \
            int r_ = e >> 3, q_ = e & 7;                                      \
            cpa16(Ks_ + r_ * 36 + q_ * 4,                                     \
                  Kb + (size_t)((JT) * 64 + r_) * (2 * C_) + q_ * 8);         \
        }                                                                     \
        _Pragma("unroll")                                                     \
        for (int i_ = 0; i_ < 2; i_++) {                                      \
            int e = tid + 256 * i_;                                           \
            int r_ = e >> 3, q_ = e & 7;                                      \
            cpa16(Vs_ + r_ * 36 + q_ * 4,                                     \
                  Vb + (size_t)r_ * N_ + (JT) * 64 + q_ * 8);                 \
        }                                                                     \
        cpa_commit();                                                         \
    } while (0)

    AT_ISSUE(0, 0);
    AT_ISSUE(1, 1);

    float mr0 = -1e30f, mr1 = -1e30f, lr0 = 0.0f, lr1 = 0.0f;
    float Oa[8][4] = {};
    unsigned qf[4][4];
    bool qf_done = false;

    for (int jt = 0; jt < 16; jt++) {
        cpa_wait1();              // Q (first iter) + KV tile jt complete
        __syncthreads();
        const uint32_t ksb = asb + (unsigned)((AT_QS + (jt & 1) * AT_KV) * 4);
        const uint32_t vsb = ksb + (unsigned)(AT_KS * 4);

        if (!qf_done) {
            qf_done = true;
            #pragma unroll
            for (int s = 0; s < 4; s++) {
                qf[s][0] = Qs[(wq + g) * 36 + 8 * s + t];
                qf[s][1] = Qs[(wq + 8 + g) * 36 + 8 * s + t];
                qf[s][2] = Qs[(wq + g) * 36 + 8 * s + t + 4];
                qf[s][3] = Qs[(wq + 8 + g) * 36 + 8 * s + t + 4];
            }
        }

        // ---- S = Q K^T ----
        float S[8][4] = {};
        #pragma unroll
        for (int s = 0; s < 4; s++) {
            #pragma unroll
            for (int ntp = 0; ntp < 4; ntp++) {
                unsigned bv[4];
                int row = ntp * 16 + mhi * 8 + mrow;
                ldsm4(bv, ksb + (unsigned)((row * 36 + s * 8 + mlo * 4) * 4));
                mma16(S[2 * ntp],     qf[s], bv);
                mma16(S[2 * ntp + 1], qf[s], bv + 2);
            }
        }

        float mx0 = -1e30f, mx1 = -1e30f;
        #pragma unroll
        for (int nt = 0; nt < 8; nt++) {
            S[nt][0] *= 0.125f; S[nt][1] *= 0.125f;
            S[nt][2] *= 0.125f; S[nt][3] *= 0.125f;
            mx0 = fmaxf(mx0, fmaxf(S[nt][0], S[nt][1]));
            mx1 = fmaxf(mx1, fmaxf(S[nt][2], S[nt][3]));
        }
        mx0 = fmaxf(mx0, __shfl_xor_sync(0xffffffffu, mx0, 1));
        mx0 = fmaxf(mx0, __shfl_xor_sync(0xffffffffu, mx0, 2));
        mx1 = fmaxf(mx1, __shfl_xor_sync(0xffffffffu, mx1, 1));
        mx1 = fmaxf(mx1, __shfl_xor_sync(0xffffffffu, mx1, 2));
        float mn0 = fmaxf(mr0, mx0), mn1 = fmaxf(mr1, mx1);
        float al0 = __expf(mr0 - mn0), al1 = __expf(mr1 - mn1);
        mr0 = mn0; mr1 = mn1;
        float s0 = 0.0f, s1 = 0.0f;
        #pragma unroll
        for (int nt = 0; nt < 8; nt++) {
            S[nt][0] = __expf(S[nt][0] - mn0);
            S[nt][1] = __expf(S[nt][1] - mn0);
            S[nt][2] = __expf(S[nt][2] - mn1);
            S[nt][3] = __expf(S[nt][3] - mn1);
            s0 += S[nt][0] + S[nt][1];
            s1 += S[nt][2] + S[nt][3];
        }
        s0 += __shfl_xor_sync(0xffffffffu, s0, 1);
        s0 += __shfl_xor_sync(0xffffffffu, s0, 2);
        s1 += __shfl_xor_sync(0xffffffffu, s1, 1);
        s1 += __shfl_xor_sync(0xffffffffu, s1, 2);
        lr0 = lr0 * al0 + s0; lr1 = lr1 * al1 + s1;

        #pragma unroll
        for (int dt = 0; dt < 8; dt++) {
            Oa[dt][0] *= al0; Oa[dt][1] *= al0;
            Oa[dt][2] *= al1; Oa[dt][3] *= al1;
        }

        // ---- O += P V ----
        #pragma unroll
        for (int s = 0; s < 4; s++) {
            unsigned pa[4] = {
                h2f(S[2 * s][0],     S[2 * s][1]),
                h2f(S[2 * s][2],     S[2 * s][3]),
                h2f(S[2 * s + 1][0], S[2 * s + 1][1]),
                h2f(S[2 * s + 1][2], S[2 * s + 1][3])
            };
            #pragma unroll
            for (int dtp = 0; dtp < 4; dtp++) {
                unsigned bv[4];
                int row = dtp * 16 + mhi * 8 + mrow;
                ldsm4(bv, vsb + (unsigned)((row * 36 + s * 8 + mlo * 4) * 4));
                mma16(Oa[2 * dtp],     pa, bv);
                mma16(Oa[2 * dtp + 1], pa, bv + 2);
            }
        }
        __syncthreads();
        if (jt + 2 < 16) AT_ISSUE(jt + 2, jt & 1);
        else             cpa_commit();
    }
    #undef AT_ISSUE

    float li0 = 1.0f / lr0, li1 = 1.0f / lr1;
    __half* r0p = Ob + (size_t)(wq + g) * C_;
    __half* r1p = Ob + (size_t)(wq + 8 + g) * C_;
    #pragma unroll
    for (int dt = 0; dt < 8; dt++) {
        int dcol = dt * 8 + 2 * t;
        *(unsigned*)(r0p + dcol) = h2f(Oa[dt][0] * li0, Oa[dt][1] * li0);
        *(unsigned*)(r1p + dcol) = h2f(Oa[dt][2] * li1, Oa[dt][3] * li1);
    }
}

// ============================================================================
// fp16 final GEMM: y = silu(BN(W_pr @ (att+pp))), f32 out  (unchanged)
// ============================================================================
__global__ __launch_bounds__(256, 2)
void gemm_add_h(const __half* __restrict__ Wt,
                const __half* __restrict__ attT,
                const __half* __restrict__ ppT,
                const float* __restrict__ gg, const float* __restrict__ bb,
                const float* __restrict__ rm, const float* __restrict__ rv,
                float* __restrict__ Y)
{
    __shared__ unsigned Ws[128 * 20];
    __shared__ unsigned Xs[128 * 20];

    const int n0 = blockIdx.x * 128;
    const int m0 = blockIdx.y * 128;
    const int b  = blockIdx.z;
    const __half* Wb = Wt + (size_t)m0 * C_;
    const __half* Ab = attT + ((size_t)b * N_ + n0) * C_;
    const __half* Pb = ppT  + ((size_t)b * N_ + n0) * C_;

    const int tid = threadIdx.x, lane = tid & 31, warp = tid >> 5;
    const int g = lane >> 2, t = lane & 3;
    const int wm = warp >> 1, wn = warp & 1;
    const int mrow = lane & 7, msel = lane >> 3;
    const int mlo = msel & 1, mhi = msel >> 1;
    const uint32_t wsb = (unsigned)__cvta_generic_to_shared(Ws);
    const uint32_t xsb = (unsigned)__cvta_generic_to_shared(Xs);

    float acc[2][8][4] = {};

    for (int ch = 0; ch < 16; ch++) {
        __syncthreads();
        #pragma unroll
        for (int i = 0; i < 2; i++) {
            int e = tid + 256 * i;
            int r = e >> 2, q = e & 3;
            cpa16(Ws + r * 20 + q * 4, Wb + (size_t)r * C_ + ch * 32 + q * 8);
        }
        cpa_commit();
        #pragma unroll
        for (int i = 0; i < 2; i++) {
            int e = tid + 256 * i;
            int r = e >> 2, q = e & 3;
            size_t off = (size_t)r * C_ + ch * 32 + q * 8;
            uint4 a4 = *(const uint4*)(Ab + off);
            uint4 p4 = *(const uint4*)(Pb + off);
            __half2* ah = (__half2*)&a4;
            __half2* ph = (__half2*)&p4;
            uint4 o;
            __half2 s0h = __hadd2(ah[0], ph[0]); o.x = *(unsigned*)&s0h;
            __half2 s1h = __hadd2(ah[1], ph[1]); o.y = *(unsigned*)&s1h;
            __half2 s2h = __hadd2(ah[2], ph[2]); o.z = *(unsigned*)&s2h;
            __half2 s3h = __hadd2(ah[3], ph[3]); o.w = *(unsigned*)&s3h;
            *(uint4*)&Xs[r * 20 + q * 4] = o;
        }
        cpa_wait0();
        __syncthreads();
        #pragma unroll
        for (int ks = 0; ks < 2; ks++) {
            unsigned a[2][4];
            #pragma unroll
            for (int mt = 0; mt < 2; mt++) {
                int row = wm * 32 + mt * 16 + mlo * 8 + mrow;
                ldsm4(a[mt], wsb + (unsigned)((row * 20 + ks * 8 + mhi * 4) * 4));
            }
            #pragma unroll
            for (int ntp = 0; ntp < 4; ntp++) {
                unsigned bv[4];
                int row = wn * 64 + ntp * 16 + mhi * 8 + mrow;
                ldsm4(bv, xsb + (unsigned)((row * 20 + ks * 8 + mlo * 4) * 4));
                mma16(acc[0][2 * ntp],     a[0], bv);
                mma16(acc[0][2 * ntp + 1], a[0], bv + 2);
                mma16(acc[1][2 * ntp],     a[1], bv);
                mma16(acc[1][2 * ntp + 1], a[1], bv + 2);
            }
        }
    }

    #pragma unroll
    for (int mt = 0; mt < 2; mt++) {
        int m  = m0 + wm * 32 + mt * 16 + g;
        int m1 = m + 8;
        float sc0 = gg[m]  * rsqrtf(rv[m]  + EPS_), sh0 = bb[m]  - rm[m]  * sc0;
        float sc1 = gg[m1] * rsqrtf(rv[m1] + EPS_), sh1 = bb[m1] - rm[m1] * sc1;
        #pragma unroll
        for (int nt = 0; nt < 8; nt++) {
            int n = n0 + wn * 64 + nt * 8 + 2 * t;
            float* c = acc[mt][nt];
            *(float2*)&Y[((size_t)b * C_ + m)  * N_ + n] =
                make_float2(silu_f(c[0] * sc0 + sh0), silu_f(c[1] * sc0 + sh0));
            *(float2*)&Y[((size_t)b * C_ + m1) * N_ + n] =
                make_float2(silu_f(c[2] * sc1 + sh1), silu_f(c[3] * sc1 + sh1));
        }
    }
}

// ============================================================================
extern "C" void kernel_launch(void* const* d_in, const int* in_sizes, int n_in,
                              void* d_out, int out_size)
{
    const float* x     = (const float*)d_in[0];
    const float* qk_w  = (const float*)d_in[1];
    const float* qk_g  = (const float*)d_in[2];
    const float* qk_b  = (const float*)d_in[3];
    const float* qk_rm = (const float*)d_in[4];
    const float* qk_rv = (const float*)d_in[5];
    const float* v_w   = (const float*)d_in[6];
    const float* v_g   = (const float*)d_in[7];
    const float* v_b   = (const float*)d_in[8];
    const float* v_rm  = (const float*)d_in[9];
    const float* v_rv  = (const float*)d_in[10];
    const float* pe_w  = (const float*)d_in[11];
    const float* pe_g  = (const float*)d_in[12];
    const float* pe_b  = (const float*)d_in[13];
    const float* pe_rm = (const float*)d_in[14];
    const float* pe_rv = (const float*)d_in[15];
    const float* pr_w  = (const float*)d_in[16];
    const float* pr_g  = (const float*)d_in[17];
    const float* pr_b  = (const float*)d_in[18];
    const float* pr_rm = (const float*)d_in[19];
    const float* pr_rv = (const float*)d_in[20];
    float* out = (float*)d_out;

    __half *p_xt, *p_wqk, *p_wv, *p_wpr, *p_wpe, *p_qkT, *p_vh, *p_vT, *p_ppT, *p_attT;
    cudaGetSymbolAddress((void**)&p_xt,   g_xt);
    cudaGetSymbolAddress((void**)&p_wqk,  g_wqkh);
    cudaGetSymbolAddress((void**)&p_wv,   g_wvh);
    cudaGetSymbolAddress((void**)&p_wpr,  g_wprh);
    cudaGetSymbolAddress((void**)&p_wpe,  g_wpeh);
    cudaGetSymbolAddress((void**)&p_qkT,  g_qkT);
    cudaGetSymbolAddress((void**)&p_vh,   g_vh);
    cudaGetSymbolAddress((void**)&p_vT,   g_vT);
    cudaGetSymbolAddress((void**)&p_ppT,  g_ppT);
    cudaGetSymbolAddress((void**)&p_attT, g_attT);

    cudaFuncSetAttribute(gemm_h,
                         cudaFuncAttributeMaxDynamicSharedMemorySize, 2 * GH_STG * 4);
    cudaFuncSetAttribute(conv3_h,
                         cudaFuncAttributeMaxDynamicSharedMemorySize, CV_SMEM);
    cudaFuncSetAttribute(attn_h,
                         cudaFuncAttributeMaxDynamicSharedMemorySize, AT_SMEM);

    dim3 thr(256);

    // 0) prep
    f2h_k<<<(2 * C_ * C_ / 8 + 255) / 256, thr>>>((const float4*)qk_w, (uint4*)p_wqk, 2 * C_ * C_ / 8);
    f2h_k<<<(C_ * C_ / 8 + 255) / 256, thr>>>((const float4*)v_w,  (uint4*)p_wv,  C_ * C_ / 8);
    f2h_k<<<(C_ * C_ / 8 + 255) / 256, thr>>>((const float4*)pr_w, (uint4*)p_wpr, C_ * C_ / 8);
    conv_w_xform_h<<<(9 * 32 * 512 * 16 + 255) / 256, thr>>>(pe_w, p_wpe);
    xpose_h<<<dim3(N_ / 32, C_ / 32, B_), dim3(32, 8)>>>(x, p_xt);

    // 1) qk -> qkT
    gemm_h<<<dim3(N_ / 128, 1024 / 128, B_), thr, 2 * GH_STG * 4>>>(
        p_wqk, p_xt, qk_g, qk_b, qk_rm, qk_rv, p_qkT, (__half*)nullptr, 1024);

    // 2) v -> vT + vh
    gemm_h<<<dim3(N_ / 128, C_ / 128, B_), thr, 2 * GH_STG * 4>>>(
        p_wv, p_xt, v_g, v_b, v_rm, v_rv, p_vT, p_vh, C_);

    // 3) conv3: vT -> ppT  (512 threads, 512px tile)
    conv3_h<<<dim3(H_ / 8, C_ / 64, B_), dim3(512), CV_SMEM>>>(
        p_wpe, p_vT, pe_g, pe_b, pe_rm, pe_rv, p_ppT);

    // 4) attention: qkT + vh -> attT
    attn_h<<<dim3(NA_ / 128, NHEAD, B_ * AREA_), thr, AT_SMEM>>>(
        p_qkT, p_vh, p_attT);

    // 5) final: W_pr @ (attT + ppT) -> out (fp32)
    gemm_add_h<<<dim3(N_ / 128, C_ / 128, B_), thr, 0>>>(
        p_wpr, p_attT, p_ppT, pr_g, pr_b, pr_rm, pr_rv, out);
}

// round 14
// speedup vs baseline: 1.0811x; 1.0811x over previous
#include <cuda_runtime.h>
#include <cuda_fp16.h>
#include <math.h>
#include <stdint.h>

#define B_    8
#define C_    512
#define H_    64
#define W_    64
#define N_    4096          // H*W
#define AREA_ 4
#define NHEAD 8
#define HD_   64
#define NA_   1024          // N/AREA
#define EPS_  1e-5f

// ---------------- scratch (device globals; no allocation allowed) ----------
__device__ __half g_xt  [B_ * N_ * C_];        // x^T  [b][n][c]
__device__ __half g_wqkh[2 * C_ * C_];         // weights, half row-major
__device__ __half g_wvh [C_ * C_];
__device__ __half g_wprh[C_ * C_];
__device__ __half g_wpeh[9 * 32 * 512 * 16];   // conv w [tap][ci][o][16]
__device__ __half g_qkT [B_ * N_ * 2 * C_];    // qk act, token-major [b][n][2C]
__device__ __half g_vh  [B_ * C_ * N_];        // v act [b][c][n]
__device__ __half g_vT  [B_ * N_ * C_];        // v act transposed [b][n][c]
__device__ __half g_ppT [B_ * N_ * C_];        // conv3 out, token-major
__device__ __half g_attT[B_ * N_ * C_];        // attention out, token-major

__device__ __forceinline__ float silu_f(float y) {
    return y / (1.0f + __expf(-y));
}
__device__ __forceinline__ unsigned h2f(float a, float b) {
    __half2 h = __floats2half2_rn(a, b);
    return *reinterpret_cast<unsigned*>(&h);
}
// D += A*B, m16n8k16 f16 in / f32 accum, row.col
__device__ __forceinline__ void mma16(float* c, const unsigned* a, const unsigned* b) {
    asm volatile(
      "mma.sync.aligned.m16n8k16.row.col.f32.f16.f16.f32 "
      "{%0,%1,%2,%3},{%4,%5,%6,%7},{%8,%9},{%0,%1,%2,%3};"
      : "+f"(c[0]), "+f"(c[1]), "+f"(c[2]), "+f"(c[3])
      : "r"(a[0]), "r"(a[1]), "r"(a[2]), "r"(a[3]), "r"(b[0]), "r"(b[1]));
}
// 4x 8x8 b16 matrices in one instruction
__device__ __forceinline__ void ldsm4(unsigned* r, uint32_t addr) {
    asm volatile("ldmatrix.sync.aligned.m8n8.x4.shared.b16 {%0,%1,%2,%3}, [%4];"
        : "=r"(r[0]), "=r"(r[1]), "=r"(r[2]), "=r"(r[3]) : "r"(addr));
}
__device__ __forceinline__ void cpa16(void* dst, const void* src) {
    unsigned d = (unsigned)__cvta_generic_to_shared(dst);
    asm volatile("cp.async.cg.shared.global [%0], [%1], 16;" :: "r"(d), "l"(src));
}
__device__ __forceinline__ void cpa16z(void* dst, const void* src, unsigned sz) {
    unsigned d = (unsigned)__cvta_generic_to_shared(dst);
    asm volatile("cp.async.cg.shared.global [%0], [%1], 16, %2;" :: "r"(d), "l"(src), "r"(sz));
}
__device__ __forceinline__ void cpa_commit() { asm volatile("cp.async.commit_group;"); }
__device__ __forceinline__ void cpa_wait1()  { asm volatile("cp.async.wait_group 1;"); }
__device__ __forceinline__ void cpa_wait0()  { asm volatile("cp.async.wait_group 0;"); }

// ============================================================================
// Prep kernels
// ============================================================================
__global__ void f2h_k(const float4* __restrict__ in, uint4* __restrict__ out, int n8)
{
    int i = blockIdx.x * blockDim.x + threadIdx.x;
    if (i < n8) {
        float4 a = in[2 * i], b = in[2 * i + 1];
        out[i] = make_uint4(h2f(a.x, a.y), h2f(a.z, a.w), h2f(b.x, b.y), h2f(b.z, b.w));
    }
}

// x [b][c][n] fp32 -> g_xt [b][n][c] half
__global__ void xpose_h(const float* __restrict__ x, __half* __restrict__ xt)
{
    __shared__ float ts[32][33];
    const int b  = blockIdx.z;
    const int c0 = blockIdx.y * 32;
    const int nb = blockIdx.x * 32;
    const int tx = threadIdx.x, ty = threadIdx.y;   // 32 x 8
    const float* xb = x + ((size_t)b * C_ + c0) * N_ + nb;
    #pragma unroll
    for (int i = 0; i < 4; i++) {
        int c = ty + i * 8;
        ts[c][tx] = xb[(size_t)c * N_ + tx];
    }
    __syncthreads();
    const int e0 = ty * 32 + tx;
    #pragma unroll
    for (int i = 0; i < 2; i++) {
        int idx = i * 256 + e0;
        int n = idx >> 4, w = idx & 15;
        unsigned word = h2f(ts[2 * w][n], ts[2 * w + 1][n]);
        ((unsigned*)(xt + ((size_t)b * N_ + nb + n) * C_ + c0))[w] = word;
    }
}

// pe_w [O][I][3][3] fp32 -> g_wpeh [tap][ci][o][16] half
__global__ void conv_w_xform_h(const float* __restrict__ pe_w, __half* __restrict__ wp)
{
    int idx = blockIdx.x * 256 + threadIdx.x;
    if (idx >= 9 * 32 * 512 * 16) return;
    int cl  = idx & 15;
    int o   = (idx >> 4) & 511;
    int ci  = (idx >> 13) & 31;
    int tap = idx >> 18;
    wp[idx] = __float2half_rn(pe_w[((size_t)o * C_ + ci * 16 + cl) * 9 + tap]);
}

// ============================================================================
// fp16 GEMM + BN + SiLU, ldmatrix fragments.  (unchanged)
// ============================================================================
#define GH_STG 5120   // words/stage: A 128*20 + B 128*20

__global__ __launch_bounds__(256, 2)
void gemm_h(const __half* __restrict__ Wt,
            const __half* __restrict__ Xt,
            const float* __restrict__ gg, const float* __restrict__ bb,
            const float* __restrict__ rm, const float* __restrict__ rv,
            __half* __restrict__ Yt,      // [b][n][M]
            __half* __restrict__ Yc,      // [b][m][N] or null
            int M)
{
    extern __shared__ unsigned sm[];     // 2 * GH_STG words

    const int n0 = blockIdx.x * 128;
    const int m0 = blockIdx.y * 128;
    const int b  = blockIdx.z;
    const __half* Wb = Wt + (size_t)m0 * C_;
    const __half* Xb = Xt + ((size_t)b * N_ + n0) * C_;

    const int tid = threadIdx.x, lane = tid & 31, warp = tid >> 5;
    const int g = lane >> 2, t = lane & 3;
    const int wm = warp >> 1, wn = warp & 1;
    const int mrow = lane & 7, msel = lane >> 3;
    const int mlo = msel & 1, mhi = msel >> 1;
    const uint32_t smb = (unsigned)__cvta_generic_to_shared(sm);

    float acc[2][8][4] = {};

    #define GH_ISSUE(CH, S) do {                                            \
        unsigned* bs = sm + (S) * GH_STG;                                   \
        _Pragma("unroll")                                                   \
        for (int i_ = 0; i_ < 4; i_++) {                                    \
            int e = tid + 256 * i_;                                         \
            int op = e >> 9, r = (e >> 2) & 127, q = e & 3;                 \
            const __half* src = (op ? Xb : Wb) + (size_t)r * C_ + (CH) * 32 + q * 8; \
            cpa16(bs + (op ? 2560 : 0) + r * 20 + q * 4, src);              \
        }                                                                   \
        cpa_commit();                                                       \
    } while (0)

    GH_ISSUE(0, 0);
    GH_ISSUE(1, 1);

    for (int ch = 0; ch < 16; ch++) {
        cpa_wait1();
        __syncthreads();
        const uint32_t sb = smb + (unsigned)((ch & 1) * (GH_STG * 4));
        const uint32_t xbse = sb + 2560 * 4;
        #pragma unroll
        for (int ks = 0; ks < 2; ks++) {
            unsigned a[2][4];
            #pragma unroll
            for (int mt = 0; mt < 2; mt++) {
                int row = wm * 32 + mt * 16 + mlo * 8 + mrow;
                ldsm4(a[mt], sb + (unsigned)((row * 20 + ks * 8 + mhi * 4) * 4));
            }
            #pragma unroll
            for (int ntp = 0; ntp < 4; ntp++) {
                unsigned bv[4];
                int row = wn * 64 + ntp * 16 + mhi * 8 + mrow;
                ldsm4(bv, xbse + (unsigned)((row * 20 + ks * 8 + mlo * 4) * 4));
                mma16(acc[0][2 * ntp],     a[0], bv);
                mma16(acc[0][2 * ntp + 1], a[0], bv + 2);
                mma16(acc[1][2 * ntp],     a[1], bv);
                mma16(acc[1][2 * ntp + 1], a[1], bv + 2);
            }
        }
        __syncthreads();
        if (ch + 2 < 16) GH_ISSUE(ch + 2, ch & 1);
        else             cpa_commit();
    }

    __half* hs = (__half*)sm;            // [128 n][136 m]
    #pragma unroll
    for (int mt = 0; mt < 2; mt++) {
        int R0 = wm * 32 + mt * 16 + g;
        int m  = m0 + R0, m1 = m + 8;
        float sc0 = gg[m]  * rsqrtf(rv[m]  + EPS_), sh0 = bb[m]  - rm[m]  * sc0;
        float sc1 = gg[m1] * rsqrtf(rv[m1] + EPS_), sh1 = bb[m1] - rm[m1] * sc1;
        #pragma unroll
        for (int nt = 0; nt < 8; nt++) {
            float* c = acc[mt][nt];
            float v0 = silu_f(c[0] * sc0 + sh0), v1 = silu_f(c[1] * sc0 + sh0);
            float v2 = silu_f(c[2] * sc1 + sh1), v3 = silu_f(c[3] * sc1 + sh1);
            int px0 = wn * 64 + nt * 8 + 2 * t;
            if (Yc) {
                *(unsigned*)(Yc + ((size_t)b * M + m)  * N_ + n0 + px0) = h2f(v0, v1);
                *(unsigned*)(Yc + ((size_t)b * M + m1) * N_ + n0 + px0) = h2f(v2, v3);
            }
            hs[px0 * 136 + R0]           = __float2half_rn(v0);
            hs[(px0 + 1) * 136 + R0]     = __float2half_rn(v1);
            hs[px0 * 136 + R0 + 8]       = __float2half_rn(v2);
            hs[(px0 + 1) * 136 + R0 + 8] = __float2half_rn(v3);
        }
    }
    __syncthreads();
    const unsigned* hw = (const unsigned*)hs;
    #pragma unroll
    for (int i = 0; i < 32; i++) {
        int e = tid + 256 * i;
        int n = e >> 6, w = e & 63;
        ((unsigned*)(Yt + ((size_t)b * N_ + n0 + n) * M + m0))[w] = hw[n * 68 + w];
    }
    #undef GH_ISSUE
}

// ============================================================================
// fp16 3x3 SAME conv + BN + SiLU, ldmatrix + 2-stage cp.async ring.
// (round-12 winner, reverted: 256 threads, 2 CTAs/SM, 256px tile)
// ============================================================================
#define CV_AW  (9 * 64 * 12)
#define CV_BX  (6 * 66 * 12)
#define CV_STG (CV_AW + CV_BX)          // 11664 words per stage
#define CV_SMEM (2 * CV_STG * 4)        // 93312 B

__global__ __launch_bounds__(256, 2)
void conv3_h(const __half* __restrict__ Wp,
             const __half* __restrict__ vT,
             const float* __restrict__ gg, const float* __restrict__ bb,
             const float* __restrict__ rm, const float* __restrict__ rv,
             __half* __restrict__ ppT)
{
    extern __shared__ unsigned cs[];    // 2 stages: [Aw | Bx]

    const int y0 = blockIdx.x * 4;
    const int m0 = blockIdx.y * 64;
    const int b  = blockIdx.z;
    const __half* vTb = vT + (size_t)b * N_ * C_;

    const int tid = threadIdx.x, lane = tid & 31, warp = tid >> 5;
    const int g = lane >> 2, t = lane & 3;
    const int wm = warp >> 2, wn = warp & 3;   // 2m x 4n
    const int mrow = lane & 7, msel = lane >> 3;
    const int mlo = msel & 1, mhi = msel >> 1;
    const uint32_t csb = (unsigned)__cvta_generic_to_shared(cs);

    float acc[2][8][4] = {};

    #define CV_ISSUE(CI, S) do {                                               \
        unsigned* Aw_ = cs + (S) * CV_STG;                                     \
        unsigned* Bx_ = Aw_ + CV_AW;                                           \
        for (int e = tid; e < 1152; e += 256) {                                \
            int tap_ = e >> 7, r_ = (e >> 1) & 63, q_ = e & 1;                 \
            cpa16(Aw_ + (tap_ * 64 + r_) * 12 + q_ * 4,                        \
                  Wp + (((size_t)tap_ * 32 + (CI)) * 512 + m0 + r_) * 16 + q_ * 8); \
        }                                                                      \
        for (int e = tid; e < 792; e += 256) {                                 \
            int r_ = e / 132, rem_ = e - r_ * 132;                             \
            int p_ = rem_ >> 1, q_ = rem_ & 1;                                 \
            int gy_ = y0 - 1 + r_, gx_ = p_ - 1;                               \
            bool ok_ = (gy_ >= 0 && gy_ < H_ && gx_ >= 0 && gx_ < W_);         \
            const __half* src_ = vTb + (ok_ ? ((size_t)(gy_ * W_ + gx_) * C_ + (CI) * 16 + q_ * 8) : 0); \
            cpa16z(Bx_ + (r_ * 66 + p_) * 12 + q_ * 4, src_, ok_ ? 16u : 0u);  \
        }                                                                      \
        cpa_commit();                                                          \
    } while (0)

    CV_ISSUE(0, 0);
    CV_ISSUE(1, 1);

    for (int ci = 0; ci < 32; ci++) {
        cpa_wait1();
        __syncthreads();
        const uint32_t awb = csb + (unsigned)((ci & 1) * (CV_STG * 4));
        const uint32_t bxb = awb + CV_AW * 4;

        for (int tap = 0; tap < 9; tap++) {
            const int dy = tap / 3, dx = tap - dy * 3;
            unsigned a[2][4];
            #pragma unroll
            for (int mt = 0; mt < 2; mt++) {
                int row = tap * 64 + wm * 32 + mt * 16 + mlo * 8 + mrow;
                ldsm4(a[mt], awb + (unsigned)((row * 12 + mhi * 4) * 4));
            }
            const int rr = wn + dy;
            #pragma unroll
            for (int ntp = 0; ntp < 4; ntp++) {
                unsigned bv[4];
                int row = rr * 66 + ntp * 16 + mhi * 8 + mrow + dx;
                ldsm4(bv, bxb + (unsigned)((row * 12 + mlo * 4) * 4));
                mma16(acc[0][2 * ntp],     a[0], bv);
                mma16(acc[0][2 * ntp + 1], a[0], bv + 2);
                mma16(acc[1][2 * ntp],     a[1], bv);
                mma16(acc[1][2 * ntp + 1], a[1], bv + 2);
            }
        }
        __syncthreads();
        if (ci + 2 < 32) CV_ISSUE(ci + 2, ci & 1);
        else             cpa_commit();
    }
    #undef CV_ISSUE

    __syncthreads();
    __half* hs = (__half*)cs;        // [256 px][72 o]
    #pragma unroll
    for (int mt = 0; mt < 2; mt++) {
        int R0 = wm * 32 + mt * 16 + g;
        int m  = m0 + R0, m1 = m + 8;
        float sc0 = gg[m]  * rsqrtf(rv[m]  + EPS_), sh0 = bb[m]  - rm[m]  * sc0;
        float sc1 = gg[m1] * rsqrtf(rv[m1] + EPS_), sh1 = bb[m1] - rm[m1] * sc1;
        #pragma unroll
        for (int nt = 0; nt < 8; nt++) {
            float* c = acc[mt][nt];
            int P0 = wn * 64 + nt * 8 + 2 * t;
            hs[P0 * 72 + R0]           = __float2half_rn(silu_f(c[0] * sc0 + sh0));
            hs[(P0 + 1) * 72 + R0]     = __float2half_rn(silu_f(c[1] * sc0 + sh0));
            hs[P0 * 72 + R0 + 8]       = __float2half_rn(silu_f(c[2] * sc1 + sh1));
            hs[(P0 + 1) * 72 + R0 + 8] = __float2half_rn(silu_f(c[3] * sc1 + sh1));
        }
    }
    __syncthreads();
    const unsigned* hw = (const unsigned*)hs;
    #pragma unroll
    for (int i = 0; i < 32; i++) {
        int e = tid + 256 * i;
        int P = e >> 5, w = e & 31;
        ((unsigned*)(ppT + ((size_t)b * N_ + y0 * W_ + P) * C_ + m0))[w] = hw[P * 36 + w];
    }
}

// ============================================================================
// fp16 area attention (FA2), ldmatrix + 2-stage KV ring. (unchanged)
// ============================================================================
#define AT_QS (128 * 36)
#define AT_KS (64 * 36)
#define AT_VS (64 * 36)
#define AT_KV (AT_KS + AT_VS)                 // 4608 words per stage
#define AT_SMEM ((AT_QS + 2 * AT_KV) * 4)     // 55296 B

__global__ __launch_bounds__(256, 2)
void attn_h(const __half* __restrict__ qkT,
            const __half* __restrict__ vh,
            __half* __restrict__ attT)
{
    extern __shared__ unsigned as_[];
    unsigned* Qs = as_;                   // [q][36]

    const int q0   = blockIdx.x * 128;
    const int head = blockIdx.y;
    const int ba   = blockIdx.z;
    const int b    = ba >> 2;
    const int area = ba & 3;
    const int atok = area * NA_;

    const __half* Qb = qkT + ((size_t)b * N_ + atok + q0) * (2 * C_) + head * HD_;
    const __half* Kb = qkT + ((size_t)b * N_ + atok) * (2 * C_) + C_ + head * HD_;
    const __half* Vb = vh  + ((size_t)b * C_ + head * HD_) * N_ + atok;
    __half*       Ob = attT + ((size_t)b * N_ + atok + q0) * C_ + head * HD_;

    const int tid = threadIdx.x, lane = tid & 31, warp = tid >> 5;
    const int g = lane >> 2, t = lane & 3;
    const int wq = warp * 16;
    const int mrow = lane & 7, msel = lane >> 3;
    const int mlo = msel & 1, mhi = msel >> 1;
    const uint32_t asb = (unsigned)__cvta_generic_to_shared(as_);

    // stage Q once: 128 rows x 32 words (its own commit group)
    #pragma unroll
    for (int i = 0; i < 4; i++) {
        int e = tid + 256 * i;
        int r = e >> 3, q = e & 7;
        cpa16(Qs + r * 36 + q * 4, Qb + (size_t)r * (2 * C_) + q * 8);
    }
    cpa_commit();

    #define AT_ISSUE(JT, S) do {                                              \
        unsigned* Ks_ = as_ + AT_QS + (S) * AT_KV;                            \
        unsigned* Vs_ = Ks_ + AT_KS;                                          \
        _Pragma("unroll")                                                     \
        for (int i_ = 0; i_ < 2; i_++) {                                      \
            int e = tid + 256 * i_;                                           \
            int r_ = e >> 3, q_ = e & 7;                                      \
            cpa16(Ks_ + r_ * 36 + q_ * 4,                                     \
                  Kb + (size_t)((JT) * 64 + r_) * (2 * C_) + q_ * 8);         \
        }                                                                     \
        _Pragma("unroll")                                                     \
        for (int i_ = 0; i_ < 2; i_++) {                                      \
            int e = tid + 256 * i_;                                           \
            int r_ = e >> 3, q_ = e & 7;                                      \
            cpa16(Vs_ + r_ * 36 + q_ * 4,                                     \
                  Vb + (size_t)r_ * N_ + (JT) * 64 + q_ * 8);                 \
        }                                                                     \
        cpa_commit();                                                         \
    } while (0)

    AT_ISSUE(0, 0);
    AT_ISSUE(1, 1);

    float mr0 = -1e30f, mr1 = -1e30f, lr0 = 0.0f, lr1 = 0.0f;
    float Oa[8][4] = {};
    unsigned qf[4][4];
    bool qf_done = false;

    for (int jt = 0; jt < 16; jt++) {
        cpa_wait1();              // Q (first iter) + KV tile jt complete
        __syncthreads();
        const uint32_t ksb = asb + (unsigned)((AT_QS + (jt & 1) * AT_KV) * 4);
        const uint32_t vsb = ksb + (unsigned)(AT_KS * 4);

        if (!qf_done) {
            qf_done = true;
            #pragma unroll
            for (int s = 0; s < 4; s++) {
                qf[s][0] = Qs[(wq + g) * 36 + 8 * s + t];
                qf[s][1] = Qs[(wq + 8 + g) * 36 + 8 * s + t];
                qf[s][2] = Qs[(wq + g) * 36 + 8 * s + t + 4];
                qf[s][3] = Qs[(wq + 8 + g) * 36 + 8 * s + t + 4];
            }
        }

        // ---- S = Q K^T ----
        float S[8][4] = {};
        #pragma unroll
        for (int s = 0; s < 4; s++) {
            #pragma unroll
            for (int ntp = 0; ntp < 4; ntp++) {
                unsigned bv[4];
                int row = ntp * 16 + mhi * 8 + mrow;
                ldsm4(bv, ksb + (unsigned)((row * 36 + s * 8 + mlo * 4) * 4));
                mma16(S[2 * ntp],     qf[s], bv);
                mma16(S[2 * ntp + 1], qf[s], bv + 2);
            }
        }

        float mx0 = -1e30f, mx1 = -1e30f;
        #pragma unroll
        for (int nt = 0; nt < 8; nt++) {
            S[nt][0] *= 0.125f; S[nt][1] *= 0.125f;
            S[nt][2] *= 0.125f; S[nt][3] *= 0.125f;
            mx0 = fmaxf(mx0, fmaxf(S[nt][0], S[nt][1]));
            mx1 = fmaxf(mx1, fmaxf(S[nt][2], S[nt][3]));
        }
        mx0 = fmaxf(mx0, __shfl_xor_sync(0xffffffffu, mx0, 1));
        mx0 = fmaxf(mx0, __shfl_xor_sync(0xffffffffu, mx0, 2));
        mx1 = fmaxf(mx1, __shfl_xor_sync(0xffffffffu, mx1, 1));
        mx1 = fmaxf(mx1, __shfl_xor_sync(0xffffffffu, mx1, 2));
        float mn0 = fmaxf(mr0, mx0), mn1 = fmaxf(mr1, mx1);
        float al0 = __expf(mr0 - mn0), al1 = __expf(mr1 - mn1);
        mr0 = mn0; mr1 = mn1;
        float s0 = 0.0f, s1 = 0.0f;
        #pragma unroll
        for (int nt = 0; nt < 8; nt++) {
            S[nt][0] = __expf(S[nt][0] - mn0);
            S[nt][1] = __expf(S[nt][1] - mn0);
            S[nt][2] = __expf(S[nt][2] - mn1);
            S[nt][3] = __expf(S[nt][3] - mn1);
            s0 += S[nt][0] + S[nt][1];
            s1 += S[nt][2] + S[nt][3];
        }
        s0 += __shfl_xor_sync(0xffffffffu, s0, 1);
        s0 += __shfl_xor_sync(0xffffffffu, s0, 2);
        s1 += __shfl_xor_sync(0xffffffffu, s1, 1);
        s1 += __shfl_xor_sync(0xffffffffu, s1, 2);
        lr0 = lr0 * al0 + s0; lr1 = lr1 * al1 + s1;

        #pragma unroll
        for (int dt = 0; dt < 8; dt++) {
            Oa[dt][0] *= al0; Oa[dt][1] *= al0;
            Oa[dt][2] *= al1; Oa[dt][3] *= al1;
        }

        // ---- O += P V ----
        #pragma unroll
        for (int s = 0; s < 4; s++) {
            unsigned pa[4] = {
                h2f(S[2 * s][0],     S[2 * s][1]),
                h2f(S[2 * s][2],     S[2 * s][3]),
                h2f(S[2 * s + 1][0], S[2 * s + 1][1]),
                h2f(S[2 * s + 1][2], S[2 * s + 1][3])
            };
            #pragma unroll
            for (int dtp = 0; dtp < 4; dtp++) {
                unsigned bv[4];
                int row = dtp * 16 + mhi * 8 + mrow;
                ldsm4(bv, vsb + (unsigned)((row * 36 + s * 8 + mlo * 4) * 4));
                mma16(Oa[2 * dtp],     pa, bv);
                mma16(Oa[2 * dtp + 1], pa, bv + 2);
            }
        }
        __syncthreads();
        if (jt + 2 < 16) AT_ISSUE(jt + 2, jt & 1);
        else             cpa_commit();
    }
    #undef AT_ISSUE

    float li0 = 1.0f / lr0, li1 = 1.0f / lr1;
    __half* r0p = Ob + (size_t)(wq + g) * C_;
    __half* r1p = Ob + (size_t)(wq + 8 + g) * C_;
    #pragma unroll
    for (int dt = 0; dt < 8; dt++) {
        int dcol = dt * 8 + 2 * t;
        *(unsigned*)(r0p + dcol) = h2f(Oa[dt][0] * li0, Oa[dt][1] * li0);
        *(unsigned*)(r1p + dcol) = h2f(Oa[dt][2] * li1, Oa[dt][3] * li1);
    }
}

// ============================================================================
// fp16 final GEMM: 2-stage ring (W via cp.async, X via register prefetch).
// ============================================================================
#define GA_STG 5120   // words/stage: Ws 128*20 + Xs 128*20

__global__ __launch_bounds__(256, 2)
void gemm_add_h(const __half* __restrict__ Wt,
                const __half* __restrict__ attT,
                const __half* __restrict__ ppT,
                const float* __restrict__ gg, const float* __restrict__ bb,
                const float* __restrict__ rm, const float* __restrict__ rv,
                float* __restrict__ Y)
{
    extern __shared__ unsigned sm[];     // 2 * GA_STG words

    const int n0 = blockIdx.x * 128;
    const int m0 = blockIdx.y * 128;
    const int b  = blockIdx.z;
    const __half* Wb = Wt + (size_t)m0 * C_;
    const __half* Ab = attT + ((size_t)b * N_ + n0) * C_;
    const __half* Pb = ppT  + ((size_t)b * N_ + n0) * C_;

    const int tid = threadIdx.x, lane = tid & 31, warp = tid >> 5;
    const int g = lane >> 2, t = lane & 3;
    const int wm = warp >> 1, wn = warp & 1;
    const int mrow = lane & 7, msel = lane >> 3;
    const int mlo = msel & 1, mhi = msel >> 1;
    const uint32_t smb = (unsigned)__cvta_generic_to_shared(sm);

    // per-thread X load coordinates (2 uint4 pairs per chunk)
    const int xr0 = tid >> 2,           xq0 = (tid & 3);
    const int xr1 = (256 + tid) >> 2,   xq1 = ((256 + tid) & 3);

    float acc[2][8][4] = {};

    #define GA_W_ISSUE(CH, S) do {                                          \
        unsigned* bs = sm + (S) * GA_STG;                                   \
        _Pragma("unroll")                                                   \
        for (int i_ = 0; i_ < 2; i_++) {                                    \
            int e = tid + 256 * i_;                                         \
            int r = e >> 2, q = e & 3;                                      \
            cpa16(bs + r * 20 + q * 4, Wb + (size_t)r * C_ + (CH) * 32 + q * 8); \
        }                                                                   \
        cpa_commit();                                                       \
    } while (0)

    // prefetch X chunk 0 into registers; issue W chunks 0,1
    uint4 xa0, xa1, xp0, xp1;
    {
        size_t o0 = (size_t)xr0 * C_ + xq0 * 8;
        size_t o1 = (size_t)xr1 * C_ + xq1 * 8;
        xa0 = *(const uint4*)(Ab + o0); xp0 = *(const uint4*)(Pb + o0);
        xa1 = *(const uint4*)(Ab + o1); xp1 = *(const uint4*)(Pb + o1);
    }
    GA_W_ISSUE(0, 0);
    GA_W_ISSUE(1, 1);

    for (int ch = 0; ch < 16; ch++) {
        // store X(ch) from registers into stage ch&1 (stage free: last used ch-2)
        {
            unsigned* Xs_ = sm + (ch & 1) * GA_STG + 2560;
            __half2* ah = (__half2*)&xa0; __half2* ph = (__half2*)&xp0;
            uint4 o;
            __half2 h0 = __hadd2(ah[0], ph[0]); o.x = *(unsigned*)&h0;
            __half2 h1 = __hadd2(ah[1], ph[1]); o.y = *(unsigned*)&h1;
            __half2 h2 = __hadd2(ah[2], ph[2]); o.z = *(unsigned*)&h2;
            __half2 h3 = __hadd2(ah[3], ph[3]); o.w = *(unsigned*)&h3;
            *(uint4*)&Xs_[xr0 * 20 + xq0 * 4] = o;
            ah = (__half2*)&xa1; ph = (__half2*)&xp1;
            __half2 h4 = __hadd2(ah[0], ph[0]); o.x = *(unsigned*)&h4;
            __half2 h5 = __hadd2(ah[1], ph[1]); o.y = *(unsigned*)&h5;
            __half2 h6 = __hadd2(ah[2], ph[2]); o.z = *(unsigned*)&h6;
            __half2 h7 = __hadd2(ah[3], ph[3]); o.w = *(unsigned*)&h7;
            *(uint4*)&Xs_[xr1 * 20 + xq1 * 4] = o;
        }
        cpa_wait1();         // W(ch) complete (W(ch+1) may remain in flight)
        __syncthreads();
        // prefetch X(ch+1) into registers (LDG latency overlaps mma below)
        if (ch + 1 < 16) {
            int kn = (ch + 1) * 32;
            size_t o0 = (size_t)xr0 * C_ + kn + xq0 * 8;
            size_t o1 = (size_t)xr1 * C_ + kn + xq1 * 8;
            xa0 = *(const uint4*)(Ab + o0); xp0 = *(const uint4*)(Pb + o0);
            xa1 = *(const uint4*)(Ab + o1); xp1 = *(const uint4*)(Pb + o1);
        }
        const uint32_t sb = smb + (unsigned)((ch & 1) * (GA_STG * 4));
        const uint32_t xbse = sb + 2560 * 4;
        #pragma unroll
        for (int ks = 0; ks < 2; ks++) {
            unsigned a[2][4];
            #pragma unroll
            for (int mt = 0; mt < 2; mt++) {
                int row = wm * 32 + mt * 16 + mlo * 8 + mrow;
                ldsm4(a[mt], sb + (unsigned)((row * 20 + ks * 8 + mhi * 4) * 4));
            }
            #pragma unroll
            for (int ntp = 0; ntp < 4; ntp++) {
                unsigned bv[4];
                int row = wn * 64 + ntp * 16 + mhi * 8 + mrow;
                ldsm4(bv, xbse + (unsigned)((row * 20 + ks * 8 + mlo * 4) * 4));
                mma16(acc[0][2 * ntp],     a[0], bv);
                mma16(acc[0][2 * ntp + 1], a[0], bv + 2);
                mma16(acc[1][2 * ntp],     a[1], bv);
                mma16(acc[1][2 * ntp + 1], a[1], bv + 2);
            }
        }
        __syncthreads();
        if (ch + 2 < 16) GA_W_ISSUE(ch + 2, ch & 1);
        else             cpa_commit();
    }
    #undef GA_W_ISSUE

    #pragma unroll
    for (int mt = 0; mt < 2; mt++) {
        int m  = m0 + wm * 32 + mt * 16 + g;
        int m1 = m + 8;
        float sc0 = gg[m]  * rsqrtf(rv[m]  + EPS_), sh0 = bb[m]  - rm[m]  * sc0;
        float sc1 = gg[m1] * rsqrtf(rv[m1] + EPS_), sh1 = bb[m1] - rm[m1] * sc1;
        #pragma unroll
        for (int nt = 0; nt < 8; nt++) {
            int n = n0 + wn * 64 + nt * 8 + 2 * t;
            float* c = acc[mt][nt];
            *(float2*)&Y[((size_t)b * C_ + m)  * N_ + n] =
                make_float2(silu_f(c[0] * sc0 + sh0), silu_f(c[1] * sc0 + sh0));
            *(float2*)&Y[((size_t)b * C_ + m1) * N_ + n] =
                make_float2(silu_f(c[2] * sc1 + sh1), silu_f(c[3] * sc1 + sh1));
        }
    }
}

// ============================================================================
extern "C" void kernel_launch(void* const* d_in, const int* in_sizes, int n_in,
                              void* d_out, int out_size)
{
    const float* x     = (const float*)d_in[0];
    const float* qk_w  = (const float*)d_in[1];
    const float* qk_g  = (const float*)d_in[2];
    const float* qk_b  = (const float*)d_in[3];
    const float* qk_rm = (const float*)d_in[4];
    const float* qk_rv = (const float*)d_in[5];
    const float* v_w   = (const float*)d_in[6];
    const float* v_g   = (const float*)d_in[7];
    const float* v_b   = (const float*)d_in[8];
    const float* v_rm  = (const float*)d_in[9];
    const float* v_rv  = (const float*)d_in[10];
    const float* pe_w  = (const float*)d_in[11];
    const float* pe_g  = (const float*)d_in[12];
    const float* pe_b  = (const float*)d_in[13];
    const float* pe_rm = (const float*)d_in[14];
    const float* pe_rv = (const float*)d_in[15];
    const float* pr_w  = (const float*)d_in[16];
    const float* pr_g  = (const float*)d_in[17];
    const float* pr_b  = (const float*)d_in[18];
    const float* pr_rm = (const float*)d_in[19];
    const float* pr_rv = (const float*)d_in[20];
    float* out = (float*)d_out;

    __half *p_xt, *p_wqk, *p_wv, *p_wpr, *p_wpe, *p_qkT, *p_vh, *p_vT, *p_ppT, *p_attT;
    cudaGetSymbolAddress((void**)&p_xt,   g_xt);
    cudaGetSymbolAddress((void**)&p_wqk,  g_wqkh);
    cudaGetSymbolAddress((void**)&p_wv,   g_wvh);
    cudaGetSymbolAddress((void**)&p_wpr,  g_wprh);
    cudaGetSymbolAddress((void**)&p_wpe,  g_wpeh);
    cudaGetSymbolAddress((void**)&p_qkT,  g_qkT);
    cudaGetSymbolAddress((void**)&p_vh,   g_vh);
    cudaGetSymbolAddress((void**)&p_vT,   g_vT);
    cudaGetSymbolAddress((void**)&p_ppT,  g_ppT);
    cudaGetSymbolAddress((void**)&p_attT, g_attT);

    cudaFuncSetAttribute(gemm_h,
                         cudaFuncAttributeMaxDynamicSharedMemorySize, 2 * GH_STG * 4);
    cudaFuncSetAttribute(conv3_h,
                         cudaFuncAttributeMaxDynamicSharedMemorySize, CV_SMEM);
    cudaFuncSetAttribute(attn_h,
                         cudaFuncAttributeMaxDynamicSharedMemorySize, AT_SMEM);
    cudaFuncSetAttribute(gemm_add_h,
                         cudaFuncAttributeMaxDynamicSharedMemorySize, 2 * GA_STG * 4);

    dim3 thr(256);

    // 0) prep
    f2h_k<<<(2 * C_ * C_ / 8 + 255) / 256, thr>>>((const float4*)qk_w, (uint4*)p_wqk, 2 * C_ * C_ / 8);
    f2h_k<<<(C_ * C_ / 8 + 255) / 256, thr>>>((const float4*)v_w,  (uint4*)p_wv,  C_ * C_ / 8);
    f2h_k<<<(C_ * C_ / 8 + 255) / 256, thr>>>((const float4*)pr_w, (uint4*)p_wpr, C_ * C_ / 8);
    conv_w_xform_h<<<(9 * 32 * 512 * 16 + 255) / 256, thr>>>(pe_w, p_wpe);
    xpose_h<<<dim3(N_ / 32, C_ / 32, B_), dim3(32, 8)>>>(x, p_xt);

    // 1) qk -> qkT
    gemm_h<<<dim3(N_ / 128, 1024 / 128, B_), thr, 2 * GH_STG * 4>>>(
        p_wqk, p_xt, qk_g, qk_b, qk_rm, qk_rv, p_qkT, (__half*)nullptr, 1024);

    // 2) v -> vT + vh
    gemm_h<<<dim3(N_ / 128, C_ / 128, B_), thr, 2 * GH_STG * 4>>>(
        p_wv, p_xt, v_g, v_b, v_rm, v_rv, p_vT, p_vh, C_);

    // 3) conv3: vT -> ppT  (round-12 config)
    conv3_h<<<dim3(H_ / 4, C_ / 64, B_), thr, CV_SMEM>>>(
        p_wpe, p_vT, pe_g, pe_b, pe_rm, pe_rv, p_ppT);

    // 4) attention: qkT + vh -> attT
    attn_h<<<dim3(NA_ / 128, NHEAD, B_ * AREA_), thr, AT_SMEM>>>(
        p_qkT, p_vh, p_attT);

    // 5) final: W_pr @ (attT + ppT) -> out (fp32)
    gemm_add_h<<<dim3(N_ / 128, C_ / 128, B_), thr, 2 * GA_STG * 4>>>(
        p_wpr, p_attT, p_ppT, pr_g, pr_b, pr_rm, pr_rv, out);
}

// round 15
// speedup vs baseline: 1.1359x; 1.0507x over previous
#include <cuda_runtime.h>
#include <cuda_fp16.h>
#include <math.h>
#include <stdint.h>

#define B_    8
#define C_    512
#define H_    64
#define W_    64
#define N_    4096          // H*W
#define AREA_ 4
#define NHEAD 8
#define HD_   64
#define NA_   1024          // N/AREA
#define EPS_  1e-5f

// ---------------- scratch (device globals; no allocation allowed) ----------
__device__ __half g_xt  [B_ * N_ * C_];        // x^T  [b][n][c]
__device__ __half g_wqkh[2 * C_ * C_];         // weights, half row-major
__device__ __half g_wvh [C_ * C_];
__device__ __half g_wprh[C_ * C_];
__device__ __half g_wpeh[9 * 32 * 512 * 16];   // conv w [tap][ci][o][16]
__device__ __half g_qkT [B_ * N_ * 2 * C_];    // qk act, token-major [b][n][2C]
__device__ __half g_vh  [B_ * C_ * N_];        // v act [b][c][n]
__device__ __half g_vT  [B_ * N_ * C_];        // v act transposed [b][n][c]
__device__ __half g_ppT [B_ * N_ * C_];        // conv3 out, token-major
__device__ __half g_attT[B_ * N_ * C_];        // attention out, token-major

__device__ __forceinline__ float silu_f(float y) {
    return y / (1.0f + __expf(-y));
}
__device__ __forceinline__ unsigned h2f(float a, float b) {
    __half2 h = __floats2half2_rn(a, b);
    return *reinterpret_cast<unsigned*>(&h);
}
// D += A*B, m16n8k16 f16 in / f32 accum, row.col
__device__ __forceinline__ void mma16(float* c, const unsigned* a, const unsigned* b) {
    asm volatile(
      "mma.sync.aligned.m16n8k16.row.col.f32.f16.f16.f32 "
      "{%0,%1,%2,%3},{%4,%5,%6,%7},{%8,%9},{%0,%1,%2,%3};"
      : "+f"(c[0]), "+f"(c[1]), "+f"(c[2]), "+f"(c[3])
      : "r"(a[0]), "r"(a[1]), "r"(a[2]), "r"(a[3]), "r"(b[0]), "r"(b[1]));
}
// 4x 8x8 b16 matrices in one instruction
__device__ __forceinline__ void ldsm4(unsigned* r, uint32_t addr) {
    asm volatile("ldmatrix.sync.aligned.m8n8.x4.shared.b16 {%0,%1,%2,%3}, [%4];"
        : "=r"(r[0]), "=r"(r[1]), "=r"(r[2]), "=r"(r[3]) : "r"(addr));
}
__device__ __forceinline__ void cpa16(void* dst, const void* src) {
    unsigned d = (unsigned)__cvta_generic_to_shared(dst);
    asm volatile("cp.async.cg.shared.global [%0], [%1], 16;" :: "r"(d), "l"(src));
}
__device__ __forceinline__ void cpa16z(void* dst, const void* src, unsigned sz) {
    unsigned d = (unsigned)__cvta_generic_to_shared(dst);
    asm volatile("cp.async.cg.shared.global [%0], [%1], 16, %2;" :: "r"(d), "l"(src), "r"(sz));
}
__device__ __forceinline__ void cpa_commit() { asm volatile("cp.async.commit_group;"); }
__device__ __forceinline__ void cpa_wait1()  { asm volatile("cp.async.wait_group 1;"); }
__device__ __forceinline__ void cpa_wait0()  { asm volatile("cp.async.wait_group 0;"); }

// ============================================================================
// Prep kernels
// ============================================================================
__global__ void f2h_k(const float4* __restrict__ in, uint4* __restrict__ out, int n8)
{
    int i = blockIdx.x * blockDim.x + threadIdx.x;
    if (i < n8) {
        float4 a = in[2 * i], b = in[2 * i + 1];
        out[i] = make_uint4(h2f(a.x, a.y), h2f(a.z, a.w), h2f(b.x, b.y), h2f(b.z, b.w));
    }
}

// x [b][c][n] fp32 -> g_xt [b][n][c] half
__global__ void xpose_h(const float* __restrict__ x, __half* __restrict__ xt)
{
    __shared__ float ts[32][33];
    const int b  = blockIdx.z;
    const int c0 = blockIdx.y * 32;
    const int nb = blockIdx.x * 32;
    const int tx = threadIdx.x, ty = threadIdx.y;   // 32 x 8
    const float* xb = x + ((size_t)b * C_ + c0) * N_ + nb;
    #pragma unroll
    for (int i = 0; i < 4; i++) {
        int c = ty + i * 8;
        ts[c][tx] = xb[(size_t)c * N_ + tx];
    }
    __syncthreads();
    const int e0 = ty * 32 + tx;
    #pragma unroll
    for (int i = 0; i < 2; i++) {
        int idx = i * 256 + e0;
        int n = idx >> 4, w = idx & 15;
        unsigned word = h2f(ts[2 * w][n], ts[2 * w + 1][n]);
        ((unsigned*)(xt + ((size_t)b * N_ + nb + n) * C_ + c0))[w] = word;
    }
}

// pe_w [O][I][3][3] fp32 -> g_wpeh [tap][ci][o][16] half
__global__ void conv_w_xform_h(const float* __restrict__ pe_w, __half* __restrict__ wp)
{
    int idx = blockIdx.x * 256 + threadIdx.x;
    if (idx >= 9 * 32 * 512 * 16) return;
    int cl  = idx & 15;
    int o   = (idx >> 4) & 511;
    int ci  = (idx >> 13) & 31;
    int tap = idx >> 18;
    wp[idx] = __float2half_rn(pe_w[((size_t)o * C_ + ci * 16 + cl) * 9 + tap]);
}

// ============================================================================
// fp16 GEMM + BN + SiLU, ldmatrix fragments.  (unchanged)
// ============================================================================
#define GH_STG 5120   // words/stage: A 128*20 + B 128*20

__global__ __launch_bounds__(256, 2)
void gemm_h(const __half* __restrict__ Wt,
            const __half* __restrict__ Xt,
            const float* __restrict__ gg, const float* __restrict__ bb,
            const float* __restrict__ rm, const float* __restrict__ rv,
            __half* __restrict__ Yt,      // [b][n][M]
            __half* __restrict__ Yc,      // [b][m][N] or null
            int M)
{
    extern __shared__ unsigned sm[];     // 2 * GH_STG words

    const int n0 = blockIdx.x * 128;
    const int m0 = blockIdx.y * 128;
    const int b  = blockIdx.z;
    const __half* Wb = Wt + (size_t)m0 * C_;
    const __half* Xb = Xt + ((size_t)b * N_ + n0) * C_;

    const int tid = threadIdx.x, lane = tid & 31, warp = tid >> 5;
    const int g = lane >> 2, t = lane & 3;
    const int wm = warp >> 1, wn = warp & 1;
    const int mrow = lane & 7, msel = lane >> 3;
    const int mlo = msel & 1, mhi = msel >> 1;
    const uint32_t smb = (unsigned)__cvta_generic_to_shared(sm);

    float acc[2][8][4] = {};

    #define GH_ISSUE(CH, S) do {                                            \
        unsigned* bs = sm + (S) * GH_STG;                                   \
        _Pragma("unroll")                                                   \
        for (int i_ = 0; i_ < 4; i_++) {                                    \
            int e = tid + 256 * i_;                                         \
            int op = e >> 9, r = (e >> 2) & 127, q = e & 3;                 \
            const __half* src = (op ? Xb : Wb) + (size_t)r * C_ + (CH) * 32 + q * 8; \
            cpa16(bs + (op ? 2560 : 0) + r * 20 + q * 4, src);              \
        }                                                                   \
        cpa_commit();                                                       \
    } while (0)

    GH_ISSUE(0, 0);
    GH_ISSUE(1, 1);

    for (int ch = 0; ch < 16; ch++) {
        cpa_wait1();
        __syncthreads();
        const uint32_t sb = smb + (unsigned)((ch & 1) * (GH_STG * 4));
        const uint32_t xbse = sb + 2560 * 4;
        #pragma unroll
        for (int ks = 0; ks < 2; ks++) {
            unsigned a[2][4];
            #pragma unroll
            for (int mt = 0; mt < 2; mt++) {
                int row = wm * 32 + mt * 16 + mlo * 8 + mrow;
                ldsm4(a[mt], sb + (unsigned)((row * 20 + ks * 8 + mhi * 4) * 4));
            }
            #pragma unroll
            for (int ntp = 0; ntp < 4; ntp++) {
                unsigned bv[4];
                int row = wn * 64 + ntp * 16 + mhi * 8 + mrow;
                ldsm4(bv, xbse + (unsigned)((row * 20 + ks * 8 + mlo * 4) * 4));
                mma16(acc[0][2 * ntp],     a[0], bv);
                mma16(acc[0][2 * ntp + 1], a[0], bv + 2);
                mma16(acc[1][2 * ntp],     a[1], bv);
                mma16(acc[1][2 * ntp + 1], a[1], bv + 2);
            }
        }
        __syncthreads();
        if (ch + 2 < 16) GH_ISSUE(ch + 2, ch & 1);
        else             cpa_commit();
    }

    __half* hs = (__half*)sm;            // [128 n][136 m]
    #pragma unroll
    for (int mt = 0; mt < 2; mt++) {
        int R0 = wm * 32 + mt * 16 + g;
        int m  = m0 + R0, m1 = m + 8;
        float sc0 = gg[m]  * rsqrtf(rv[m]  + EPS_), sh0 = bb[m]  - rm[m]  * sc0;
        float sc1 = gg[m1] * rsqrtf(rv[m1] + EPS_), sh1 = bb[m1] - rm[m1] * sc1;
        #pragma unroll
        for (int nt = 0; nt < 8; nt++) {
            float* c = acc[mt][nt];
            float v0 = silu_f(c[0] * sc0 + sh0), v1 = silu_f(c[1] * sc0 + sh0);
            float v2 = silu_f(c[2] * sc1 + sh1), v3 = silu_f(c[3] * sc1 + sh1);
            int px0 = wn * 64 + nt * 8 + 2 * t;
            if (Yc) {
                *(unsigned*)(Yc + ((size_t)b * M + m)  * N_ + n0 + px0) = h2f(v0, v1);
                *(unsigned*)(Yc + ((size_t)b * M + m1) * N_ + n0 + px0) = h2f(v2, v3);
            }
            hs[px0 * 136 + R0]           = __float2half_rn(v0);
            hs[(px0 + 1) * 136 + R0]     = __float2half_rn(v1);
            hs[px0 * 136 + R0 + 8]       = __float2half_rn(v2);
            hs[(px0 + 1) * 136 + R0 + 8] = __float2half_rn(v3);
        }
    }
    __syncthreads();
    const unsigned* hw = (const unsigned*)hs;
    #pragma unroll
    for (int i = 0; i < 32; i++) {
        int e = tid + 256 * i;
        int n = e >> 6, w = e & 63;
        ((unsigned*)(Yt + ((size_t)b * N_ + n0 + n) * M + m0))[w] = hw[n * 68 + w];
    }
    #undef GH_ISSUE
}

// ============================================================================
// fp16 3x3 SAME conv + BN + SiLU, ldmatrix + 2-stage cp.async ring.
// (round-12/14 winner: 256 threads, 2 CTAs/SM, 256px tile)
// ============================================================================
#define CV_AW  (9 * 64 * 12)
#define CV_BX  (6 * 66 * 12)
#define CV_STG (CV_AW + CV_BX)          // 11664 words per stage
#define CV_SMEM (2 * CV_STG * 4)        // 93312 B

__global__ __launch_bounds__(256, 2)
void conv3_h(const __half* __restrict__ Wp,
             const __half* __restrict__ vT,
             const float* __restrict__ gg, const float* __restrict__ bb,
             const float* __restrict__ rm, const float* __restrict__ rv,
             __half* __restrict__ ppT)
{
    extern __shared__ unsigned cs[];    // 2 stages: [Aw | Bx]

    const int y0 = blockIdx.x * 4;
    const int m0 = blockIdx.y * 64;
    const int b  = blockIdx.z;
    const __half* vTb = vT + (size_t)b * N_ * C_;

    const int tid = threadIdx.x, lane = tid & 31, warp = tid >> 5;
    const int g = lane >> 2, t = lane & 3;
    const int wm = warp >> 2, wn = warp & 3;   // 2m x 4n
    const int mrow = lane & 7, msel = lane >> 3;
    const int mlo = msel & 1, mhi = msel >> 1;
    const uint32_t csb = (unsigned)__cvta_generic_to_shared(cs);

    float acc[2][8][4] = {};

    #define CV_ISSUE(CI, S) do {                                               \
        unsigned* Aw_ = cs + (S) * CV_STG;                                     \
        unsigned* Bx_ = Aw_ + CV_AW;                                           \
        for (int e = tid; e < 1152; e += 256) {                                \
            int tap_ = e >> 7, r_ = (e >> 1) & 63, q_ = e & 1;                 \
            cpa16(Aw_ + (tap_ * 64 + r_) * 12 + q_ * 4,                        \
                  Wp + (((size_t)tap_ * 32 + (CI)) * 512 + m0 + r_) * 16 + q_ * 8); \
        }                                                                      \
        for (int e = tid; e < 792; e += 256) {                                 \
            int r_ = e / 132, rem_ = e - r_ * 132;                             \
            int p_ = rem_ >> 1, q_ = rem_ & 1;                                 \
            int gy_ = y0 - 1 + r_, gx_ = p_ - 1;                               \
            bool ok_ = (gy_ >= 0 && gy_ < H_ && gx_ >= 0 && gx_ < W_);         \
            const __half* src_ = vTb + (ok_ ? ((size_t)(gy_ * W_ + gx_) * C_ + (CI) * 16 + q_ * 8) : 0); \
            cpa16z(Bx_ + (r_ * 66 + p_) * 12 + q_ * 4, src_, ok_ ? 16u : 0u);  \
        }                                                                      \
        cpa_commit();                                                          \
    } while (0)

    CV_ISSUE(0, 0);
    CV_ISSUE(1, 1);

    for (int ci = 0; ci < 32; ci++) {
        cpa_wait1();
        __syncthreads();
        const uint32_t awb = csb + (unsigned)((ci & 1) * (CV_STG * 4));
        const uint32_t bxb = awb + CV_AW * 4;

        for (int tap = 0; tap < 9; tap++) {
            const int dy = tap / 3, dx = tap - dy * 3;
            unsigned a[2][4];
            #pragma unroll
            for (int mt = 0; mt < 2; mt++) {
                int row = tap * 64 + wm * 32 + mt * 16 + mlo * 8 + mrow;
                ldsm4(a[mt], awb + (unsigned)((row * 12 + mhi * 4) * 4));
            }
            const int rr = wn + dy;
            #pragma unroll
            for (int ntp = 0; ntp < 4; ntp++) {
                unsigned bv[4];
                int row = rr * 66 + ntp * 16 + mhi * 8 + mrow + dx;
                ldsm4(bv, bxb + (unsigned)((row * 12 + mlo * 4) * 4));
                mma16(acc[0][2 * ntp],     a[0], bv);
                mma16(acc[0][2 * ntp + 1], a[0], bv + 2);
                mma16(acc[1][2 * ntp],     a[1], bv);
                mma16(acc[1][2 * ntp + 1], a[1], bv + 2);
            }
        }
        __syncthreads();
        if (ci + 2 < 32) CV_ISSUE(ci + 2, ci & 1);
        else             cpa_commit();
    }
    #undef CV_ISSUE

    __syncthreads();
    __half* hs = (__half*)cs;        // [256 px][72 o]
    #pragma unroll
    for (int mt = 0; mt < 2; mt++) {
        int R0 = wm * 32 + mt * 16 + g;
        int m  = m0 + R0, m1 = m + 8;
        float sc0 = gg[m]  * rsqrtf(rv[m]  + EPS_), sh0 = bb[m]  - rm[m]  * sc0;
        float sc1 = gg[m1] * rsqrtf(rv[m1] + EPS_), sh1 = bb[m1] - rm[m1] * sc1;
        #pragma unroll
        for (int nt = 0; nt < 8; nt++) {
            float* c = acc[mt][nt];
            int P0 = wn * 64 + nt * 8 + 2 * t;
            hs[P0 * 72 + R0]           = __float2half_rn(silu_f(c[0] * sc0 + sh0));
            hs[(P0 + 1) * 72 + R0]     = __float2half_rn(silu_f(c[1] * sc0 + sh0));
            hs[P0 * 72 + R0 + 8]       = __float2half_rn(silu_f(c[2] * sc1 + sh1));
            hs[(P0 + 1) * 72 + R0 + 8] = __float2half_rn(silu_f(c[3] * sc1 + sh1));
        }
    }
    __syncthreads();
    const unsigned* hw = (const unsigned*)hs;
    #pragma unroll
    for (int i = 0; i < 32; i++) {
        int e = tid + 256 * i;
        int P = e >> 5, w = e & 31;
        ((unsigned*)(ppT + ((size_t)b * N_ + y0 * W_ + P) * C_ + m0))[w] = hw[P * 36 + w];
    }
}

// ============================================================================
// fp16 area attention (FA2), ldmatrix + 2-stage KV ring. (unchanged)
// ============================================================================
#define AT_QS (128 * 36)
#define AT_KS (64 * 36)
#define AT_VS (64 * 36)
#define AT_KV (AT_KS + AT_VS)                 // 4608 words per stage
#define AT_SMEM ((AT_QS + 2 * AT_KV) * 4)     // 55296 B

__global__ __launch_bounds__(256, 2)
void attn_h(const __half* __restrict__ qkT,
            const __half* __restrict__ vh,
            __half* __restrict__ attT)
{
    extern __shared__ unsigned as_[];
    unsigned* Qs = as_;                   // [q][36]

    const int q0   = blockIdx.x * 128;
    const int head = blockIdx.y;
    const int ba   = blockIdx.z;
    const int b    = ba >> 2;
    const int area = ba & 3;
    const int atok = area * NA_;

    const __half* Qb = qkT + ((size_t)b * N_ + atok + q0) * (2 * C_) + head * HD_;
    const __half* Kb = qkT + ((size_t)b * N_ + atok) * (2 * C_) + C_ + head * HD_;
    const __half* Vb = vh  + ((size_t)b * C_ + head * HD_) * N_ + atok;
    __half*       Ob = attT + ((size_t)b * N_ + atok + q0) * C_ + head * HD_;

    const int tid = threadIdx.x, lane = tid & 31, warp = tid >> 5;
    const int g = lane >> 2, t = lane & 3;
    const int wq = warp * 16;
    const int mrow = lane & 7, msel = lane >> 3;
    const int mlo = msel & 1, mhi = msel >> 1;
    const uint32_t asb = (unsigned)__cvta_generic_to_shared(as_);

    // stage Q once: 128 rows x 32 words (its own commit group)
    #pragma unroll
    for (int i = 0; i < 4; i++) {
        int e = tid + 256 * i;
        int r = e >> 3, q = e & 7;
        cpa16(Qs + r * 36 + q * 4, Qb + (size_t)r * (2 * C_) + q * 8);
    }
    cpa_commit();

    #define AT_ISSUE(JT, S) do {                                              \
        unsigned* Ks_ = as_ + AT_QS + (S) * AT_KV;                            \
        unsigned* Vs_ = Ks_ + AT_KS;                                          \
        _Pragma("unroll")                                                     \
        for (int i_ = 0; i_ < 2; i_++) {                                      \
            int e = tid + 256 * i_;                                           \
            int r_ = e >> 3, q_ = e & 7;                                      \
            cpa16(Ks_ + r_ * 36 + q_ * 4,                                     \
                  Kb + (size_t)((JT) * 64 + r_) * (2 * C_) + q_ * 8);         \
        }                                                                     \
        _Pragma("unroll")                                                     \
        for (int i_ = 0; i_ < 2; i_++) {                                      \
            int e = tid + 256 * i_;                                           \
            int r_ = e >> 3, q_ = e & 7;                                      \
            cpa16(Vs_ + r_ * 36 + q_ * 4,                                     \
                  Vb + (size_t)r_ * N_ + (JT) * 64 + q_ * 8);                 \
        }                                                                     \
        cpa_commit();                                                         \
    } while (0)

    AT_ISSUE(0, 0);
    AT_ISSUE(1, 1);

    float mr0 = -1e30f, mr1 = -1e30f, lr0 = 0.0f, lr1 = 0.0f;
    float Oa[8][4] = {};
    unsigned qf[4][4];
    bool qf_done = false;

    for (int jt = 0; jt < 16; jt++) {
        cpa_wait1();              // Q (first iter) + KV tile jt complete
        __syncthreads();
        const uint32_t ksb = asb + (unsigned)((AT_QS + (jt & 1) * AT_KV) * 4);
        const uint32_t vsb = ksb + (unsigned)(AT_KS * 4);

        if (!qf_done) {
            qf_done = true;
            #pragma unroll
            for (int s = 0; s < 4; s++) {
                qf[s][0] = Qs[(wq + g) * 36 + 8 * s + t];
                qf[s][1] = Qs[(wq + 8 + g) * 36 + 8 * s + t];
                qf[s][2] = Qs[(wq + g) * 36 + 8 * s + t + 4];
                qf[s][3] = Qs[(wq + 8 + g) * 36 + 8 * s + t + 4];
            }
        }

        // ---- S = Q K^T ----
        float S[8][4] = {};
        #pragma unroll
        for (int s = 0; s < 4; s++) {
            #pragma unroll
            for (int ntp = 0; ntp < 4; ntp++) {
                unsigned bv[4];
                int row = ntp * 16 + mhi * 8 + mrow;
                ldsm4(bv, ksb + (unsigned)((row * 36 + s * 8 + mlo * 4) * 4));
                mma16(S[2 * ntp],     qf[s], bv);
                mma16(S[2 * ntp + 1], qf[s], bv + 2);
            }
        }

        float mx0 = -1e30f, mx1 = -1e30f;
        #pragma unroll
        for (int nt = 0; nt < 8; nt++) {
            S[nt][0] *= 0.125f; S[nt][1] *= 0.125f;
            S[nt][2] *= 0.125f; S[nt][3] *= 0.125f;
            mx0 = fmaxf(mx0, fmaxf(S[nt][0], S[nt][1]));
            mx1 = fmaxf(mx1, fmaxf(S[nt][2], S[nt][3]));
        }
        mx0 = fmaxf(mx0, __shfl_xor_sync(0xffffffffu, mx0, 1));
        mx0 = fmaxf(mx0, __shfl_xor_sync(0xffffffffu, mx0, 2));
        mx1 = fmaxf(mx1, __shfl_xor_sync(0xffffffffu, mx1, 1));
        mx1 = fmaxf(mx1, __shfl_xor_sync(0xffffffffu, mx1, 2));
        float mn0 = fmaxf(mr0, mx0), mn1 = fmaxf(mr1, mx1);
        float al0 = __expf(mr0 - mn0), al1 = __expf(mr1 - mn1);
        mr0 = mn0; mr1 = mn1;
        float s0 = 0.0f, s1 = 0.0f;
        #pragma unroll
        for (int nt = 0; nt < 8; nt++) {
            S[nt][0] = __expf(S[nt][0] - mn0);
            S[nt][1] = __expf(S[nt][1] - mn0);
            S[nt][2] = __expf(S[nt][2] - mn1);
            S[nt][3] = __expf(S[nt][3] - mn1);
            s0 += S[nt][0] + S[nt][1];
            s1 += S[nt][2] + S[nt][3];
        }
        s0 += __shfl_xor_sync(0xffffffffu, s0, 1);
        s0 += __shfl_xor_sync(0xffffffffu, s0, 2);
        s1 += __shfl_xor_sync(0xffffffffu, s1, 1);
        s1 += __shfl_xor_sync(0xffffffffu, s1, 2);
        lr0 = lr0 * al0 + s0; lr1 = lr1 * al1 + s1;

        #pragma unroll
        for (int dt = 0; dt < 8; dt++) {
            Oa[dt][0] *= al0; Oa[dt][1] *= al0;
            Oa[dt][2] *= al1; Oa[dt][3] *= al1;
        }

        // ---- O += P V ----
        #pragma unroll
        for (int s = 0; s < 4; s++) {
            unsigned pa[4] = {
                h2f(S[2 * s][0],     S[2 * s][1]),
                h2f(S[2 * s][2],     S[2 * s][3]),
                h2f(S[2 * s + 1][0], S[2 * s + 1][1]),
                h2f(S[2 * s + 1][2], S[2 * s + 1][3])
            };
            #pragma unroll
            for (int dtp = 0; dtp < 4; dtp++) {
                unsigned bv[4];
                int row = dtp * 16 + mhi * 8 + mrow;
                ldsm4(bv, vsb + (unsigned)((row * 36 + s * 8 + mlo * 4) * 4));
                mma16(Oa[2 * dtp],     pa, bv);
                mma16(Oa[2 * dtp + 1], pa, bv + 2);
            }
        }
        __syncthreads();
        if (jt + 2 < 16) AT_ISSUE(jt + 2, jt & 1);
        else             cpa_commit();
    }
    #undef AT_ISSUE

    float li0 = 1.0f / lr0, li1 = 1.0f / lr1;
    __half* r0p = Ob + (size_t)(wq + g) * C_;
    __half* r1p = Ob + (size_t)(wq + 8 + g) * C_;
    #pragma unroll
    for (int dt = 0; dt < 8; dt++) {
        int dcol = dt * 8 + 2 * t;
        *(unsigned*)(r0p + dcol) = h2f(Oa[dt][0] * li0, Oa[dt][1] * li0);
        *(unsigned*)(r1p + dcol) = h2f(Oa[dt][2] * li1, Oa[dt][3] * li1);
    }
}

// ============================================================================
// fp16 final GEMM: 2-stage ring (W via cp.async, X via register prefetch).
// ============================================================================
#define GA_STG 5120   // words/stage: Ws 128*20 + Xs 128*20

__global__ __launch_bounds__(256, 2)
void gemm_add_h(const __half* __restrict__ Wt,
                const __half* __restrict__ attT,
                const __half* __restrict__ ppT,
                const float* __restrict__ gg, const float* __restrict__ bb,
                const float* __restrict__ rm, const float* __restrict__ rv,
                float* __restrict__ Y)
{
    extern __shared__ unsigned sm[];     // 2 * GA_STG words

    const int n0 = blockIdx.x * 128;
    const int m0 = blockIdx.y * 128;
    const int b  = blockIdx.z;
    const __half* Wb = Wt + (size_t)m0 * C_;
    const __half* Ab = attT + ((size_t)b * N_ + n0) * C_;
    const __half* Pb = ppT  + ((size_t)b * N_ + n0) * C_;

    const int tid = threadIdx.x, lane = tid & 31, warp = tid >> 5;
    const int g = lane >> 2, t = lane & 3;
    const int wm = warp >> 1, wn = warp & 1;
    const int mrow = lane & 7, msel = lane >> 3;
    const int mlo = msel & 1, mhi = msel >> 1;
    const uint32_t smb = (unsigned)__cvta_generic_to_shared(sm);

    const int xr0 = tid >> 2,           xq0 = (tid & 3);
    const int xr1 = (256 + tid) >> 2,   xq1 = ((256 + tid) & 3);

    float acc[2][8][4] = {};

    #define GA_W_ISSUE(CH, S) do {                                          \
        unsigned* bs = sm + (S) * GA_STG;                                   \
        _Pragma("unroll")                                                   \
        for (int i_ = 0; i_ < 2; i_++) {                                    \
            int e = tid + 256 * i_;                                         \
            int r = e >> 2, q = e & 3;                                      \
            cpa16(bs + r * 20 + q * 4, Wb + (size_t)r * C_ + (CH) * 32 + q * 8); \
        }                                                                   \
        cpa_commit();                                                       \
    } while (0)

    uint4 xa0, xa1, xp0, xp1;
    {
        size_t o0 = (size_t)xr0 * C_ + xq0 * 8;
        size_t o1 = (size_t)xr1 * C_ + xq1 * 8;
        xa0 = *(const uint4*)(Ab + o0); xp0 = *(const uint4*)(Pb + o0);
        xa1 = *(const uint4*)(Ab + o1); xp1 = *(const uint4*)(Pb + o1);
    }
    GA_W_ISSUE(0, 0);
    GA_W_ISSUE(1, 1);

    for (int ch = 0; ch < 16; ch++) {
        {
            unsigned* Xs_ = sm + (ch & 1) * GA_STG + 2560;
            __half2* ah = (__half2*)&xa0; __half2* ph = (__half2*)&xp0;
            uint4 o;
            __half2 h0 = __hadd2(ah[0], ph[0]); o.x = *(unsigned*)&h0;
            __half2 h1 = __hadd2(ah[1], ph[1]); o.y = *(unsigned*)&h1;
            __half2 h2 = __hadd2(ah[2], ph[2]); o.z = *(unsigned*)&h2;
            __half2 h3 = __hadd2(ah[3], ph[3]); o.w = *(unsigned*)&h3;
            *(uint4*)&Xs_[xr0 * 20 + xq0 * 4] = o;
            ah = (__half2*)&xa1; ph = (__half2*)&xp1;
            __half2 h4 = __hadd2(ah[0], ph[0]); o.x = *(unsigned*)&h4;
            __half2 h5 = __hadd2(ah[1], ph[1]); o.y = *(unsigned*)&h5;
            __half2 h6 = __hadd2(ah[2], ph[2]); o.z = *(unsigned*)&h6;
            __half2 h7 = __hadd2(ah[3], ph[3]); o.w = *(unsigned*)&h7;
            *(uint4*)&Xs_[xr1 * 20 + xq1 * 4] = o;
        }
        cpa_wait1();
        __syncthreads();
        if (ch + 1 < 16) {
            int kn = (ch + 1) * 32;
            size_t o0 = (size_t)xr0 * C_ + kn + xq0 * 8;
            size_t o1 = (size_t)xr1 * C_ + kn + xq1 * 8;
            xa0 = *(const uint4*)(Ab + o0); xp0 = *(const uint4*)(Pb + o0);
            xa1 = *(const uint4*)(Ab + o1); xp1 = *(const uint4*)(Pb + o1);
        }
        const uint32_t sb = smb + (unsigned)((ch & 1) * (GA_STG * 4));
        const uint32_t xbse = sb + 2560 * 4;
        #pragma unroll
        for (int ks = 0; ks < 2; ks++) {
            unsigned a[2][4];
            #pragma unroll
            for (int mt = 0; mt < 2; mt++) {
                int row = wm * 32 + mt * 16 + mlo * 8 + mrow;
                ldsm4(a[mt], sb + (unsigned)((row * 20 + ks * 8 + mhi * 4) * 4));
            }
            #pragma unroll
            for (int ntp = 0; ntp < 4; ntp++) {
                unsigned bv[4];
                int row = wn * 64 + ntp * 16 + mhi * 8 + mrow;
                ldsm4(bv, xbse + (unsigned)((row * 20 + ks * 8 + mlo * 4) * 4));
                mma16(acc[0][2 * ntp],     a[0], bv);
                mma16(acc[0][2 * ntp + 1], a[0], bv + 2);
                mma16(acc[1][2 * ntp],     a[1], bv);
                mma16(acc[1][2 * ntp + 1], a[1], bv + 2);
            }
        }
        __syncthreads();
        if (ch + 2 < 16) GA_W_ISSUE(ch + 2, ch & 1);
        else             cpa_commit();
    }
    #undef GA_W_ISSUE

    #pragma unroll
    for (int mt = 0; mt < 2; mt++) {
        int m  = m0 + wm * 32 + mt * 16 + g;
        int m1 = m + 8;
        float sc0 = gg[m]  * rsqrtf(rv[m]  + EPS_), sh0 = bb[m]  - rm[m]  * sc0;
        float sc1 = gg[m1] * rsqrtf(rv[m1] + EPS_), sh1 = bb[m1] - rm[m1] * sc1;
        #pragma unroll
        for (int nt = 0; nt < 8; nt++) {
            int n = n0 + wn * 64 + nt * 8 + 2 * t;
            float* c = acc[mt][nt];
            *(float2*)&Y[((size_t)b * C_ + m)  * N_ + n] =
                make_float2(silu_f(c[0] * sc0 + sh0), silu_f(c[1] * sc0 + sh0));
            *(float2*)&Y[((size_t)b * C_ + m1) * N_ + n] =
                make_float2(silu_f(c[2] * sc1 + sh1), silu_f(c[3] * sc1 + sh1));
        }
    }
}

// ============================================================================
extern "C" void kernel_launch(void* const* d_in, const int* in_sizes, int n_in,
                              void* d_out, int out_size)
{
    const float* x     = (const float*)d_in[0];
    const float* qk_w  = (const float*)d_in[1];
    const float* qk_g  = (const float*)d_in[2];
    const float* qk_b  = (const float*)d_in[3];
    const float* qk_rm = (const float*)d_in[4];
    const float* qk_rv = (const float*)d_in[5];
    const float* v_w   = (const float*)d_in[6];
    const float* v_g   = (const float*)d_in[7];
    const float* v_b   = (const float*)d_in[8];
    const float* v_rm  = (const float*)d_in[9];
    const float* v_rv  = (const float*)d_in[10];
    const float* pe_w  = (const float*)d_in[11];
    const float* pe_g  = (const float*)d_in[12];
    const float* pe_b  = (const float*)d_in[13];
    const float* pe_rm = (const float*)d_in[14];
    const float* pe_rv = (const float*)d_in[15];
    const float* pr_w  = (const float*)d_in[16];
    const float* pr_g  = (const float*)d_in[17];
    const float* pr_b  = (const float*)d_in[18];
    const float* pr_rm = (const float*)d_in[19];
    const float* pr_rv = (const float*)d_in[20];
    float* out = (float*)d_out;

    __half *p_xt, *p_wqk, *p_wv, *p_wpr, *p_wpe, *p_qkT, *p_vh, *p_vT, *p_ppT, *p_attT;
    cudaGetSymbolAddress((void**)&p_xt,   g_xt);
    cudaGetSymbolAddress((void**)&p_wqk,  g_wqkh);
    cudaGetSymbolAddress((void**)&p_wv,   g_wvh);
    cudaGetSymbolAddress((void**)&p_wpr,  g_wprh);
    cudaGetSymbolAddress((void**)&p_wpe,  g_wpeh);
    cudaGetSymbolAddress((void**)&p_qkT,  g_qkT);
    cudaGetSymbolAddress((void**)&p_vh,   g_vh);
    cudaGetSymbolAddress((void**)&p_vT,   g_vT);
    cudaGetSymbolAddress((void**)&p_ppT,  g_ppT);
    cudaGetSymbolAddress((void**)&p_attT, g_attT);

    cudaFuncSetAttribute(gemm_h,
                         cudaFuncAttributeMaxDynamicSharedMemorySize, 2 * GH_STG * 4);
    cudaFuncSetAttribute(conv3_h,
                         cudaFuncAttributeMaxDynamicSharedMemorySize, CV_SMEM);
    cudaFuncSetAttribute(attn_h,
                         cudaFuncAttributeMaxDynamicSharedMemorySize, AT_SMEM);
    cudaFuncSetAttribute(gemm_add_h,
                         cudaFuncAttributeMaxDynamicSharedMemorySize, 2 * GA_STG * 4);

    // fork/join streams + events (host objects; created fresh per call,
    // never destroyed so capture references stay valid; kernel_launch is
    // invoked only a handful of times, never in the timed replay loop)
    cudaStream_t s1;
    cudaStreamCreateWithFlags(&s1, cudaStreamNonBlocking);
    cudaEvent_t evP, evV, evC;
    cudaEventCreateWithFlags(&evP, cudaEventDisableTiming);
    cudaEventCreateWithFlags(&evV, cudaEventDisableTiming);
    cudaEventCreateWithFlags(&evC, cudaEventDisableTiming);

    dim3 thr(256);

    // 0) prep on stream 0
    f2h_k<<<(2 * C_ * C_ / 8 + 255) / 256, thr>>>((const float4*)qk_w, (uint4*)p_wqk, 2 * C_ * C_ / 8);
    f2h_k<<<(C_ * C_ / 8 + 255) / 256, thr>>>((const float4*)v_w,  (uint4*)p_wv,  C_ * C_ / 8);
    f2h_k<<<(C_ * C_ / 8 + 255) / 256, thr>>>((const float4*)pr_w, (uint4*)p_wpr, C_ * C_ / 8);
    conv_w_xform_h<<<(9 * 32 * 512 * 16 + 255) / 256, thr>>>(pe_w, p_wpe);
    xpose_h<<<dim3(N_ / 32, C_ / 32, B_), dim3(32, 8)>>>(x, p_xt);
    cudaEventRecord(evP, 0);

    // fork: s1 runs  v -> conv3 ;  stream 0 runs  qk -> attn
    cudaStreamWaitEvent(s1, evP, 0);

    // s1: v GEMM then conv3
    gemm_h<<<dim3(N_ / 128, C_ / 128, B_), thr, 2 * GH_STG * 4, s1>>>(
        p_wv, p_xt, v_g, v_b, v_rm, v_rv, p_vT, p_vh, C_);
    cudaEventRecord(evV, s1);
    conv3_h<<<dim3(H_ / 4, C_ / 64, B_), thr, CV_SMEM, s1>>>(
        p_wpe, p_vT, pe_g, pe_b, pe_rm, pe_rv, p_ppT);
    cudaEventRecord(evC, s1);

    // stream 0: qk GEMM, then attention (needs v output too)
    gemm_h<<<dim3(N_ / 128, 1024 / 128, B_), thr, 2 * GH_STG * 4>>>(
        p_wqk, p_xt, qk_g, qk_b, qk_rm, qk_rv, p_qkT, (__half*)nullptr, 1024);
    cudaStreamWaitEvent(0, evV, 0);
    attn_h<<<dim3(NA_ / 128, NHEAD, B_ * AREA_), thr, AT_SMEM>>>(
        p_qkT, p_vh, p_attT);

    // join: gemm_add needs attn (stream 0) + conv3 (s1)
    cudaStreamWaitEvent(0, evC, 0);
    gemm_add_h<<<dim3(N_ / 128, C_ / 128, B_), thr, 2 * GA_STG * 4>>>(
        p_wpr, p_attT, p_ppT, pr_g, pr_b, pr_rm, pr_rv, out);
}